// round 9
// baseline (speedup 1.0000x reference)
#include <cuda_runtime.h>
#include <cuda_fp16.h>
#include <cstdint>

#define BB 32
#define TT 4096
#define PP 512
#define WW 128
#define NMEL 80
#define FILT 256
#define PDIM 64
#define KK 9
#define PAD 4

#define STR 40                        // smem row stride (fp16), conflict-free
#define A_ROWS 136                    // 128 + 2*PAD halo
#define A_CP (A_ROWS * STR)           // 5440 elems per copy
#define B_CP (FILT * STR)             // 10240 elems per stage
#define OFF_B (4 * A_CP)              // 21760: A = 2 chunkbufs x (hi,mid)
#define CONV_SMEM 131072              // max(mainloop 104960, staging 128KB) -> 1 CTA/SM

// ---------------- device scratch ----------------------------------------------------
__device__ __half g_melhi[(size_t)BB * TT * 96];
__device__ __half g_melmid[(size_t)BB * TT * 96];
__device__ __half g_x1hi[(size_t)BB * TT * FILT];
__device__ __half g_x1mid[(size_t)BB * TT * FILT];
__device__ float g_x2[(size_t)BB * TT * FILT];
__device__ __half g_w1h[KK * FILT * 96];
__device__ __half g_w2h[KK * FILT * FILT];
__device__ float g_ph[(size_t)BB * PP * FILT];
__device__ float g_wd[(size_t)BB * WW * FILT];
__device__ float g_z [(size_t)BB * WW * PDIM];
__device__ int   g_pcum[BB * PP];
__device__ int   g_wcum[BB * WW];

// ---------------- helpers ------------------------------------------------------------
__device__ __forceinline__ uint32_t smem_u32(const void* p) {
    return (uint32_t)__cvta_generic_to_shared(p);
}
#define CP16(dst_u32, src_ptr) \
    asm volatile("cp.async.cg.shared.global [%0], [%1], 16;" :: "r"(dst_u32), "l"(src_ptr) : "memory")
#define CP_COMMIT() asm volatile("cp.async.commit_group;" ::: "memory")
#define CP_WAIT0()  asm volatile("cp.async.wait_group 0;" ::: "memory")
#define CP_WAIT1()  asm volatile("cp.async.wait_group 1;" ::: "memory")

#define MMA_F16(d, a, b) \
    asm volatile("mma.sync.aligned.m16n8k16.row.col.f32.f16.f16.f32 " \
        "{%0,%1,%2,%3},{%4,%5,%6,%7},{%8,%9},{%0,%1,%2,%3};" \
        : "+f"((d)[0]), "+f"((d)[1]), "+f"((d)[2]), "+f"((d)[3]) \
        : "r"((a)[0]), "r"((a)[1]), "r"((a)[2]), "r"((a)[3]), "r"((b)[0]), "r"((b)[1]))

#define LDM4(r0, r1, r2, r3, addr) \
    asm volatile("ldmatrix.sync.aligned.m8n8.x4.shared.b16 {%0,%1,%2,%3}, [%4];" \
        : "=r"(r0), "=r"(r1), "=r"(r2), "=r"(r3) : "r"(addr))

__device__ __forceinline__ uint32_t pack_hi2(float x0, float x1) {
    __half2 t(__float2half_rn(x0), __float2half_rn(x1));
    return *reinterpret_cast<uint32_t*>(&t);
}
__device__ __forceinline__ uint32_t pack_mid2(float x0, float x1) {
    float h0 = __half2float(__float2half_rn(x0));
    float h1 = __half2float(__float2half_rn(x1));
    __half2 t(__float2half_rn(x0 - h0), __float2half_rn(x1 - h1));
    return *reinterpret_cast<uint32_t*>(&t);
}

// ---------------- prep kernels -------------------------------------------------------
__global__ void mel_split_kernel(const float* __restrict__ mels) {
    size_t i = (size_t)blockIdx.x * blockDim.x + threadIdx.x;
    if (i < (size_t)BB * TT * 96) {
        size_t t = i / 96;
        int ci = (int)(i % 96);
        float x = (ci < NMEL) ? mels[t * NMEL + ci] : 0.f;
        __half h = __float2half_rn(x);
        g_melhi[i] = h;
        g_melmid[i] = __float2half_rn(x - __half2float(h));
    }
}
template <int CIN, int CINP>
__global__ void wsplit_kernel(const float* __restrict__ w, __half* __restrict__ wh) {
    int i = blockIdx.x * blockDim.x + threadIdx.x;      // [tap][co][ci-padded]
    if (i < KK * FILT * CINP) {
        int ci = i % CINP;
        int co = (i / CINP) % FILT;
        int tap = i / (CINP * FILT);
        float x = (ci < CIN) ? w[(co * CIN + ci) * KK + tap] : 0.f;
        wh[i] = __float2half_rn(x);
    }
}
__global__ void scan_kernel(const int* __restrict__ dur, const int* __restrict__ wpl) {
    int b = blockIdx.x, lane = threadIdx.x;
    int v[16], s = 0;
#pragma unroll
    for (int i = 0; i < 16; i++) { v[i] = dur[b * PP + lane * 16 + i]; s += v[i]; }
    int inc = s;
#pragma unroll
    for (int off = 1; off < 32; off <<= 1) {
        int t = __shfl_up_sync(0xffffffffu, inc, off);
        if (lane >= off) inc += t;
    }
    int base = inc - s, run = 0;
#pragma unroll
    for (int i = 0; i < 16; i++) { run += v[i]; g_pcum[b * PP + lane * 16 + i] = base + run; }
    int w[4]; s = 0;
#pragma unroll
    for (int i = 0; i < 4; i++) { w[i] = wpl[b * WW + lane * 4 + i]; s += w[i]; }
    inc = s;
#pragma unroll
    for (int off = 1; off < 32; off <<= 1) {
        int t = __shfl_up_sync(0xffffffffu, inc, off);
        if (lane >= off) inc += t;
    }
    base = inc - s; run = 0;
#pragma unroll
    for (int i = 0; i < 4; i++) { run += w[i]; g_wcum[b * WW + lane * 4 + i] = base + run; }
}

// ---------------- fused conv(fp16x2) + bias + relu + LN, M=128 x N=256, 512 thr ------
// MODE 0: write fp16 hi/mid.  MODE 1: write fp32.
template <int NCH, int MODE>
__global__ void __launch_bounds__(512, 1) conv_fused(
    const __half* __restrict__ Ahi, const __half* __restrict__ Amid,
    const __half* __restrict__ Bh16,
    const float* __restrict__ bias, const float* __restrict__ gamma,
    const float* __restrict__ beta,
    float* __restrict__ outf, __half* __restrict__ outh, __half* __restrict__ outm)
{
    constexpr int CINP = NCH * 32;
    constexpr int NST = NCH * KK;
    extern __shared__ __half smhf[];
    __shared__ float sB[FILT], sG[FILT], sE[FILT];
    __shared__ float s_m[128], s_r[128];

    const int tid = threadIdx.x;
    const int wid = tid >> 5, lane = tid & 31;
    const int wm = wid & 1, wn = wid >> 1;              // 2m x 8n warps
    const int t0 = blockIdx.x * 128;
    const size_t bT = (size_t)blockIdx.y * TT;
    const uint32_t smb = smem_u32(smhf);

    if (tid < FILT) { sB[tid] = bias[tid]; sG[tid] = gamma[tid]; sE[tid] = beta[tid]; }

    float acc[4][4][4];
#pragma unroll
    for (int mt = 0; mt < 4; mt++)
#pragma unroll
        for (int nt = 0; nt < 4; nt++)
#pragma unroll
            for (int q = 0; q < 4; q++) acc[mt][nt][q] = 0.f;

    // ldmatrix lane offsets
    const int a_l = ((lane >> 3) & 1) * 8 + (lane & 7);
    const int a_k = (lane >> 4) * 8;
    const int b_l = (lane >> 4) * 8 + (lane & 7);
    const int b_k = ((lane >> 3) & 1) * 8;
    uint32_t aoff[4], boff[2];
#pragma unroll
    for (int mt = 0; mt < 4; mt++)
        aoff[mt] = ((wm * 64 + mt * 16 + a_l) * STR + a_k) * 2;
#pragma unroll
    for (int np = 0; np < 2; np++)
        boff[np] = ((wn * 32 + np * 16 + b_l) * STR + b_k) * 2;

    auto issue_loads = [&](int s) {
        int chunk = s / KK, tap = s - chunk * KK;
        __half* sBp = smhf + OFF_B + (s % 3) * B_CP;
#pragma unroll
        for (int j = 0; j < 2; j++) {
            int q = tid + j * 512;                      // 0..1023 = 256 rows x 4
            int row = q >> 2, c16 = q & 3;
            const __half* src = Bh16
                + ((size_t)tap * FILT + row) * CINP + chunk * 32 + c16 * 8;
            CP16(smem_u32(sBp + row * STR + c16 * 8), src);
        }
        if (tap == 0) {
            __half* sA = smhf + (chunk & 1) * (2 * A_CP);
#pragma unroll
            for (int j = 0; j < 3; j++) {
                int q = tid + j * 512;
                if (q < 2 * 4 * A_ROWS) {               // 1088
                    int copy = (q >= 4 * A_ROWS) ? 1 : 0;
                    int rem = q - copy * 4 * A_ROWS;
                    int row = rem >> 2, c16 = rem & 3;
                    int trow = t0 + row - PAD;
                    __half* dst = sA + copy * A_CP + row * STR + c16 * 8;
                    if (trow >= 0 && trow < TT) {
                        const __half* src = (copy ? Amid : Ahi)
                            + (bT + trow) * CINP + chunk * 32 + c16 * 8;
                        CP16(smem_u32(dst), src);
                    } else {
                        *(uint4*)dst = make_uint4(0, 0, 0, 0);
                    }
                }
            }
        }
    };

    issue_loads(0); CP_COMMIT();
    issue_loads(1); CP_COMMIT();

    for (int s = 0; s < NST; s++) {
        if (s + 1 < NST) CP_WAIT1(); else CP_WAIT0();
        __syncthreads();
        if (s + 2 < NST) { issue_loads(s + 2); CP_COMMIT(); }

        int chunk = s / KK, tap = s - chunk * KK;
        uint32_t aAh = smb + (chunk & 1) * (2 * A_CP * 2) + tap * (STR * 2);
        uint32_t aAm = aAh + A_CP * 2;
        uint32_t aB  = smb + (OFF_B + (s % 3) * B_CP) * 2;

#pragma unroll
        for (int kk = 0; kk < 2; kk++) {
            uint32_t ah[4][4], bh[4][2];
#pragma unroll
            for (int mt = 0; mt < 4; mt++)
                LDM4(ah[mt][0], ah[mt][1], ah[mt][2], ah[mt][3], aAh + aoff[mt] + kk * 32);
#pragma unroll
            for (int np = 0; np < 2; np++)
                LDM4(bh[2 * np][0], bh[2 * np][1], bh[2 * np + 1][0], bh[2 * np + 1][1],
                     aB + boff[np] + kk * 32);
#pragma unroll
            for (int mt = 0; mt < 4; mt++)
#pragma unroll
                for (int nt = 0; nt < 4; nt++) MMA_F16(acc[mt][nt], ah[mt], bh[nt]);

#pragma unroll
            for (int mt = 0; mt < 4; mt++)
                LDM4(ah[mt][0], ah[mt][1], ah[mt][2], ah[mt][3], aAm + aoff[mt] + kk * 32);
#pragma unroll
            for (int mt = 0; mt < 4; mt++)
#pragma unroll
                for (int nt = 0; nt < 4; nt++) MMA_F16(acc[mt][nt], ah[mt], bh[nt]);
        }
    }
    __syncthreads();

    // ---------------- fused epilogue: bias + relu -> smem; LN; write ----------------
    float* st = (float*)smhf;                 // 128 x 256 fp32 = 128 KB
    const int r = lane >> 2, cq = lane & 3;
#pragma unroll
    for (int mt = 0; mt < 4; mt++) {
        int R0 = wm * 64 + mt * 16 + r;
#pragma unroll
        for (int nt = 0; nt < 4; nt++) {
            int C = wn * 32 + nt * 8 + 2 * cq;
            st[R0 * FILT + C]           = fmaxf(acc[mt][nt][0] + sB[C], 0.f);
            st[R0 * FILT + C + 1]       = fmaxf(acc[mt][nt][1] + sB[C + 1], 0.f);
            st[(R0 + 8) * FILT + C]     = fmaxf(acc[mt][nt][2] + sB[C], 0.f);
            st[(R0 + 8) * FILT + C + 1] = fmaxf(acc[mt][nt][3] + sB[C + 1], 0.f);
        }
    }
    __syncthreads();

    // per-row LN stats: warp w handles rows 8w..8w+7 (deterministic, no atomics)
#pragma unroll
    for (int rr = 0; rr < 8; rr++) {
        int row = wid * 8 + rr;
        float4 u = ((const float4*)st)[row * 64 + lane];
        float4 v = ((const float4*)st)[row * 64 + lane + 32];
        float s = u.x + u.y + u.z + u.w + v.x + v.y + v.z + v.w;
        float q = u.x * u.x + u.y * u.y + u.z * u.z + u.w * u.w
                + v.x * v.x + v.y * v.y + v.z * v.z + v.w * v.w;
#pragma unroll
        for (int off = 16; off > 0; off >>= 1) {
            s += __shfl_xor_sync(0xffffffffu, s, off);
            q += __shfl_xor_sync(0xffffffffu, q, off);
        }
        if (lane == 0) {
            float m = s * (1.f / FILT);
            s_m[row] = m;
            s_r[row] = rsqrtf(q * (1.f / FILT) - m * m + 1e-5f);
        }
    }
    __syncthreads();

#pragma unroll
    for (int j = 0; j < 16; j++) {
        int f4 = tid + j * 512;               // 8192 float4 = 128x256
        int row = f4 >> 6, c4 = f4 & 63;
        float4 v = ((const float4*)st)[f4];
        float m = s_m[row], rs = s_r[row];
        int C = c4 * 4;
        float y0 = (v.x - m) * rs * sG[C]     + sE[C];
        float y1 = (v.y - m) * rs * sG[C + 1] + sE[C + 1];
        float y2 = (v.z - m) * rs * sG[C + 2] + sE[C + 2];
        float y3 = (v.w - m) * rs * sG[C + 3] + sE[C + 3];
        size_t o = (bT + t0 + row) * FILT + C;
        if (MODE == 1) {
            *(float4*)(outf + o) = make_float4(y0, y1, y2, y3);
        } else {
            *(uint2*)(outh + o) = make_uint2(pack_hi2(y0, y1), pack_hi2(y2, y3));
            *(uint2*)(outm + o) = make_uint2(pack_mid2(y0, y1), pack_mid2(y2, y3));
        }
    }
}

// ---------------- pooling / mlp / expand --------------------------------------------
__global__ void phone_pool_kernel(const int* __restrict__ dur) {
    int b = blockIdx.y, p = blockIdx.x, c = threadIdx.x;
    int start = p ? g_pcum[b * PP + p - 1] : 0;
    int end = g_pcum[b * PP + p];
    if (start > TT) start = TT;
    if (end > TT) end = TT;
    float s = 0.f;
    for (int t = start; t < end; t++) s += g_x2[((size_t)(b * TT + t)) * FILT + c];
    int d = dur[b * PP + p]; if (d < 1) d = 1;
    g_ph[((size_t)(b * PP + p)) * FILT + c] = s / (float)d;
}
__global__ void word_pool_kernel(const int* __restrict__ wpl) {
    int b = blockIdx.y, w = blockIdx.x, c = threadIdx.x;
    int start = w ? g_wcum[b * WW + w - 1] : 0;
    int end = g_wcum[b * WW + w];
    if (start > PP) start = PP;
    if (end > PP) end = PP;
    float s = 0.f;
    for (int p = start; p < end; p++) s += g_ph[((size_t)(b * PP + p)) * FILT + c];
    int d = wpl[b * WW + w]; if (d < 1) d = 1;
    g_wd[((size_t)(b * WW + w)) * FILT + c] = s / (float)d;
}
__global__ void __launch_bounds__(256) mlp_kernel(
    const float* __restrict__ w1, const float* __restrict__ b1,
    const float* __restrict__ w2, const float* __restrict__ b2)
{
    __shared__ float sh[32 * FILT];
    int b = blockIdx.y, w0 = blockIdx.x * 32, o = threadIdx.x;
    for (int idx = o; idx < 32 * FILT; idx += 256)
        sh[idx] = g_wd[((size_t)(b * WW + w0)) * FILT + idx];
    __syncthreads();
    float acc[32];
    float bv = b1[o];
#pragma unroll
    for (int m = 0; m < 32; m++) acc[m] = bv;
    for (int i = 0; i < FILT; i++) {
        float wv = w1[i * FILT + o];
#pragma unroll
        for (int m = 0; m < 32; m++) acc[m] += sh[m * FILT + i] * wv;
    }
    __syncthreads();
#pragma unroll
    for (int m = 0; m < 32; m++) sh[m * FILT + o] = fmaxf(acc[m], 0.f);
    __syncthreads();
    int oo = o & (PDIM - 1);
    int mg = o >> 6;
    for (int m = mg * 8; m < mg * 8 + 8; m++) {
        float a = b2[oo];
        for (int i = 0; i < FILT; i++) a += sh[m * FILT + i] * w2[i * PDIM + oo];
        g_z[((size_t)(b * WW + w0 + m)) * PDIM + oo] = fmaxf(a, 0.f);
    }
}
__global__ void expand_kernel(const unsigned char* __restrict__ mask, float* __restrict__ out) {
    int b = blockIdx.y, p = blockIdx.x, o = threadIdx.x;
    const int* wc = g_wcum + b * WW;
    int lo = 0, hi = WW;
    while (lo < hi) { int mid = (lo + hi) >> 1; if (wc[mid] <= p) lo = mid + 1; else hi = mid; }
    int wid = lo; if (wid > WW - 1) wid = WW - 1;
    float v = g_z[((size_t)(b * WW + wid)) * PDIM + o];
    if (mask[b * PP + p]) v = 0.f;
    out[((size_t)(b * PP + p)) * PDIM + o] = v;
}

// ---------------- host launch -------------------------------------------------------
extern "C" void kernel_launch(void* const* d_in, const int* in_sizes, int n_in,
                              void* d_out, int out_size)
{
    const unsigned char* mask = (const unsigned char*)d_in[0];
    const float* mels = (const float*)d_in[1];
    const int* durations = (const int*)d_in[3];
    const int* wpl = (const int*)d_in[4];
    const float* c1w = (const float*)d_in[5];
    const float* c1b = (const float*)d_in[6];
    const float* l1g = (const float*)d_in[7];
    const float* l1b = (const float*)d_in[8];
    const float* c2w = (const float*)d_in[9];
    const float* c2b = (const float*)d_in[10];
    const float* l2g = (const float*)d_in[11];
    const float* l2b = (const float*)d_in[12];
    const float* w1 = (const float*)d_in[13];
    const float* b1 = (const float*)d_in[14];
    const float* w2 = (const float*)d_in[15];
    const float* b2 = (const float*)d_in[16];
    float* out = (float*)d_out;

    void *p_melhi, *p_melmid, *p_x1hi, *p_x1mid, *p_x2, *p_w1h, *p_w2h;
    cudaGetSymbolAddress(&p_melhi, g_melhi);
    cudaGetSymbolAddress(&p_melmid, g_melmid);
    cudaGetSymbolAddress(&p_x1hi, g_x1hi);
    cudaGetSymbolAddress(&p_x1mid, g_x1mid);
    cudaGetSymbolAddress(&p_x2, g_x2);
    cudaGetSymbolAddress(&p_w1h, g_w1h);
    cudaGetSymbolAddress(&p_w2h, g_w2h);

    cudaFuncSetAttribute(conv_fused<3, 0>, cudaFuncAttributeMaxDynamicSharedMemorySize, CONV_SMEM);
    cudaFuncSetAttribute(conv_fused<8, 1>, cudaFuncAttributeMaxDynamicSharedMemorySize, CONV_SMEM);

    mel_split_kernel<<<(int)(((size_t)BB * TT * 96 + 255) / 256), 256>>>(mels);
    wsplit_kernel<NMEL, 96><<<(KK * FILT * 96 + 255) / 256, 256>>>(c1w, (__half*)p_w1h);
    wsplit_kernel<FILT, FILT><<<(KK * FILT * FILT + 255) / 256, 256>>>(c2w, (__half*)p_w2h);
    scan_kernel<<<BB, 32>>>(durations, wpl);

    dim3 cgrid(TT / 128, BB);
    conv_fused<3, 0><<<cgrid, 512, CONV_SMEM>>>(
        (const __half*)p_melhi, (const __half*)p_melmid, (const __half*)p_w1h,
        c1b, l1g, l1b, nullptr, (__half*)p_x1hi, (__half*)p_x1mid);
    conv_fused<8, 1><<<cgrid, 512, CONV_SMEM>>>(
        (const __half*)p_x1hi, (const __half*)p_x1mid, (const __half*)p_w2h,
        c2b, l2g, l2b, (float*)p_x2, nullptr, nullptr);

    phone_pool_kernel<<<dim3(PP, BB), FILT>>>(durations);
    word_pool_kernel<<<dim3(WW, BB), FILT>>>(wpl);
    mlp_kernel<<<dim3(WW / 32, BB), 256>>>(w1, b1, w2, b2);
    expand_kernel<<<dim3(PP, BB), PDIM>>>(mask, out);
}

// round 10
// speedup vs baseline: 1.1122x; 1.1122x over previous
#include <cuda_runtime.h>
#include <cuda_fp16.h>
#include <cstdint>

#define BB 32
#define TT 4096
#define PP 512
#define WW 128
#define NMEL 80
#define FILT 256
#define PDIM 64
#define KK 9
#define PAD 4

#define STR 40                        // smem row stride (fp16), conflict-free
#define A_ROWS 136                    // 128 + 2*PAD halo
#define A_CP 5440                     // A_ROWS*STR elems per copy
#define B_CP 5120                     // 128*STR elems
#define OFF_B 21760                   // A = 2 chunkbufs x (hi,mid)
#define CONV_SMEM ((OFF_B + 3 * B_CP) * 2)    // 74240 bytes -> 2 CTAs/SM

// ---------------- device scratch ----------------------------------------------------
__device__ __half g_melhi[(size_t)BB * TT * 96];
__device__ __half g_melmid[(size_t)BB * TT * 96];
__device__ __half g_x1hi[(size_t)BB * TT * FILT];
__device__ __half g_x1mid[(size_t)BB * TT * FILT];
__device__ float g_craw[(size_t)BB * TT * FILT];
__device__ float g_x2[(size_t)BB * TT * FILT];
__device__ __half g_w1h[KK * FILT * 96];
__device__ __half g_w2h[KK * FILT * FILT];
__device__ float g_ph[(size_t)BB * PP * FILT];
__device__ float g_wd[(size_t)BB * WW * FILT];
__device__ float g_z [(size_t)BB * WW * PDIM];
__device__ int   g_pcum[BB * PP];
__device__ int   g_wcum[BB * WW];

// ---------------- helpers ------------------------------------------------------------
__device__ __forceinline__ uint32_t smem_u32(const void* p) {
    return (uint32_t)__cvta_generic_to_shared(p);
}
#define CP16(dst_u32, src_ptr) \
    asm volatile("cp.async.cg.shared.global [%0], [%1], 16;" :: "r"(dst_u32), "l"(src_ptr) : "memory")
#define CP_COMMIT() asm volatile("cp.async.commit_group;" ::: "memory")
#define CP_WAIT0()  asm volatile("cp.async.wait_group 0;" ::: "memory")
#define CP_WAIT1()  asm volatile("cp.async.wait_group 1;" ::: "memory")

#define MMA_F16(d, a, b) \
    asm volatile("mma.sync.aligned.m16n8k16.row.col.f32.f16.f16.f32 " \
        "{%0,%1,%2,%3},{%4,%5,%6,%7},{%8,%9},{%0,%1,%2,%3};" \
        : "+f"((d)[0]), "+f"((d)[1]), "+f"((d)[2]), "+f"((d)[3]) \
        : "r"((a)[0]), "r"((a)[1]), "r"((a)[2]), "r"((a)[3]), "r"((b)[0]), "r"((b)[1]))

#define LDM4(r0, r1, r2, r3, addr) \
    asm volatile("ldmatrix.sync.aligned.m8n8.x4.shared.b16 {%0,%1,%2,%3}, [%4];" \
        : "=r"(r0), "=r"(r1), "=r"(r2), "=r"(r3) : "r"(addr))

__device__ __forceinline__ uint32_t pack_hi2(float x0, float x1) {
    __half2 t(__float2half_rn(x0), __float2half_rn(x1));
    return *reinterpret_cast<uint32_t*>(&t);
}
__device__ __forceinline__ uint32_t pack_mid2(float x0, float x1) {
    float h0 = __half2float(__float2half_rn(x0));
    float h1 = __half2float(__float2half_rn(x1));
    __half2 t(__float2half_rn(x0 - h0), __float2half_rn(x1 - h1));
    return *reinterpret_cast<uint32_t*>(&t);
}

// ---------------- prep kernels -------------------------------------------------------
__global__ void mel_split_kernel(const float* __restrict__ mels) {
    size_t i = (size_t)blockIdx.x * blockDim.x + threadIdx.x;
    if (i < (size_t)BB * TT * 96) {
        size_t t = i / 96;
        int ci = (int)(i % 96);
        float x = (ci < NMEL) ? mels[t * NMEL + ci] : 0.f;
        __half h = __float2half_rn(x);
        g_melhi[i] = h;
        g_melmid[i] = __float2half_rn(x - __half2float(h));
    }
}
template <int CIN, int CINP>
__global__ void wsplit_kernel(const float* __restrict__ w, __half* __restrict__ wh) {
    int i = blockIdx.x * blockDim.x + threadIdx.x;      // [tap][co][ci-padded]
    if (i < KK * FILT * CINP) {
        int ci = i % CINP;
        int co = (i / CINP) % FILT;
        int tap = i / (CINP * FILT);
        float x = (ci < CIN) ? w[(co * CIN + ci) * KK + tap] : 0.f;
        wh[i] = __float2half_rn(x);
    }
}
__global__ void scan_kernel(const int* __restrict__ dur, const int* __restrict__ wpl) {
    int b = blockIdx.x, lane = threadIdx.x;             // 32 threads/block
    int v[16], s = 0;
#pragma unroll
    for (int i = 0; i < 16; i++) { v[i] = dur[b * PP + lane * 16 + i]; s += v[i]; }
    int inc = s;
#pragma unroll
    for (int off = 1; off < 32; off <<= 1) {
        int t = __shfl_up_sync(0xffffffffu, inc, off);
        if (lane >= off) inc += t;
    }
    int base = inc - s, run = 0;
#pragma unroll
    for (int i = 0; i < 16; i++) { run += v[i]; g_pcum[b * PP + lane * 16 + i] = base + run; }
    int w[4]; s = 0;
#pragma unroll
    for (int i = 0; i < 4; i++) { w[i] = wpl[b * WW + lane * 4 + i]; s += w[i]; }
    inc = s;
#pragma unroll
    for (int off = 1; off < 32; off <<= 1) {
        int t = __shfl_up_sync(0xffffffffu, inc, off);
        if (lane >= off) inc += t;
    }
    base = inc - s; run = 0;
#pragma unroll
    for (int i = 0; i < 4; i++) { run += w[i]; g_wcum[b * WW + lane * 4 + i] = base + run; }
}

// ---------------- conv via fp16x2 mma.sync, halo-resident A, 2 CTAs/SM ---------------
// CIN = true input channels; chunks of 32 with a possible 16-wide tail (conv1: 80).
template <int NCH, int CIN>
__global__ void __launch_bounds__(256, 2) conv_mma(
    const __half* __restrict__ Ahi, const __half* __restrict__ Amid,
    const __half* __restrict__ Bh16,
    float* __restrict__ outc)
{
    constexpr int CINP = NCH * 32;
    constexpr int NST = NCH * KK;
    extern __shared__ __half smhf[];

    const int tid = threadIdx.x;
    const int wid = tid >> 5, lane = tid & 31;
    const int wm = wid & 1, wn = wid >> 1;              // 2m x 4n warps
    const int t0 = blockIdx.x * 128;
    const int n0 = blockIdx.y * 128;
    const size_t bT = (size_t)blockIdx.z * TT;
    const uint32_t smb = smem_u32(smhf);

    float acc[4][4][4];
#pragma unroll
    for (int mt = 0; mt < 4; mt++)
#pragma unroll
        for (int nt = 0; nt < 4; nt++)
#pragma unroll
            for (int q = 0; q < 4; q++) acc[mt][nt][q] = 0.f;

    // ldmatrix lane offsets
    const int a_l = ((lane >> 3) & 1) * 8 + (lane & 7);
    const int a_k = (lane >> 4) * 8;
    const int b_l = (lane >> 4) * 8 + (lane & 7);
    const int b_k = ((lane >> 3) & 1) * 8;
    uint32_t aoff[4], boff[2];
#pragma unroll
    for (int mt = 0; mt < 4; mt++)
        aoff[mt] = ((wm * 64 + mt * 16 + a_l) * STR + a_k) * 2;
#pragma unroll
    for (int np = 0; np < 2; np++)
        boff[np] = ((wn * 32 + np * 16 + b_l) * STR + b_k) * 2;

    auto issue_loads = [&](int s) {
        int chunk = s / KK, tap = s - chunk * KK;
        int kc = CIN - chunk * 32; if (kc > 32) kc = 32;     // 16-wide tail chunk
        __half* sB = smhf + OFF_B + (s % 3) * B_CP;
#pragma unroll
        for (int j = 0; j < 2; j++) {
            int q = tid + j * 256;                      // 0..511
            int row = q >> 2, c16 = q & 3;
            if (c16 * 8 < kc) {
                const __half* src = Bh16
                    + ((size_t)tap * FILT + n0 + row) * CINP + chunk * 32 + c16 * 8;
                CP16(smem_u32(sB + row * STR + c16 * 8), src);
            }
        }
        if (tap == 0) {
            __half* sA = smhf + (chunk & 1) * (2 * A_CP);
#pragma unroll
            for (int j = 0; j < 5; j++) {
                int q = tid + j * 256;
                if (q < 1088) {
                    int copy = (q >= 544) ? 1 : 0;
                    int rem = q - copy * 544;
                    int row = rem >> 2, c16 = rem & 3;
                    if (c16 * 8 >= kc) continue;
                    int trow = t0 + row - PAD;
                    __half* dst = sA + copy * A_CP + row * STR + c16 * 8;
                    if (trow >= 0 && trow < TT) {
                        const __half* src = (copy ? Amid : Ahi)
                            + (bT + trow) * CINP + chunk * 32 + c16 * 8;
                        CP16(smem_u32(dst), src);
                    } else {
                        *(uint4*)dst = make_uint4(0, 0, 0, 0);
                    }
                }
            }
        }
    };

    issue_loads(0); CP_COMMIT();
    issue_loads(1); CP_COMMIT();

    for (int s = 0; s < NST; s++) {
        if (s + 1 < NST) CP_WAIT1(); else CP_WAIT0();
        __syncthreads();
        if (s + 2 < NST) { issue_loads(s + 2); CP_COMMIT(); }

        int chunk = s / KK, tap = s - chunk * KK;
        uint32_t aAh = smb + (chunk & 1) * (2 * A_CP * 2) + tap * (STR * 2);
        uint32_t aAm = aAh + A_CP * 2;
        uint32_t aBh = smb + (OFF_B + (s % 3) * B_CP) * 2;

        auto do_kk = [&](int kk) {
            uint32_t ah[4][4], bh[4][2];
#pragma unroll
            for (int mt = 0; mt < 4; mt++)
                LDM4(ah[mt][0], ah[mt][1], ah[mt][2], ah[mt][3], aAh + aoff[mt] + kk * 32);
#pragma unroll
            for (int np = 0; np < 2; np++)
                LDM4(bh[2 * np][0], bh[2 * np][1], bh[2 * np + 1][0], bh[2 * np + 1][1],
                     aBh + boff[np] + kk * 32);
#pragma unroll
            for (int mt = 0; mt < 4; mt++)
#pragma unroll
                for (int nt = 0; nt < 4; nt++) MMA_F16(acc[mt][nt], ah[mt], bh[nt]);

#pragma unroll
            for (int mt = 0; mt < 4; mt++)
                LDM4(ah[mt][0], ah[mt][1], ah[mt][2], ah[mt][3], aAm + aoff[mt] + kk * 32);
#pragma unroll
            for (int mt = 0; mt < 4; mt++)
#pragma unroll
                for (int nt = 0; nt < 4; nt++) MMA_F16(acc[mt][nt], ah[mt], bh[nt]);
        };

        do_kk(0);
        bool full = (CIN - chunk * 32) >= 32;           // tail chunk has only k16
        if (full) do_kk(1);
    }
    __syncthreads();

    // ---------------- epilogue: stage to smem, coalesced store ----------------------
    float* st = (float*)smhf;                 // 64 KB staging (fits in 74240)
    const int r = lane >> 2, cq = lane & 3;
#pragma unroll
    for (int mt = 0; mt < 4; mt++) {
        int R0 = wm * 64 + mt * 16 + r;
#pragma unroll
        for (int nt = 0; nt < 4; nt++) {
            int C = wn * 32 + nt * 8 + 2 * cq;
            st[R0 * 128 + C]           = acc[mt][nt][0];
            st[R0 * 128 + C + 1]       = acc[mt][nt][1];
            st[(R0 + 8) * 128 + C]     = acc[mt][nt][2];
            st[(R0 + 8) * 128 + C + 1] = acc[mt][nt][3];
        }
    }
    __syncthreads();
#pragma unroll
    for (int i = 0; i < 16; i++) {
        int f4 = tid + i * 256;               // 4096 float4 = 128x128
        int row = f4 >> 5, c4 = f4 & 31;
        *(float4*)(outc + (bT + t0 + row) * FILT + n0 + c4 * 4) = ((float4*)st)[f4];
    }
}

// ---------------- bias + relu + LN pass (warp per frame) ----------------------------
template <int MODE>    // 0: write fp16 hi/mid.  1: write fp32
__global__ void __launch_bounds__(256) ln_kernel(
    const float* __restrict__ gc,
    const float* __restrict__ bias, const float* __restrict__ gamma,
    const float* __restrict__ beta,
    float* __restrict__ outf,
    __half* __restrict__ outh, __half* __restrict__ outm)
{
    __shared__ float sB[FILT], sG[FILT], sE[FILT];
    int tid = threadIdx.x;
    if (tid < FILT) { sB[tid] = bias[tid]; sG[tid] = gamma[tid]; sE[tid] = beta[tid]; }
    __syncthreads();

    int wid = tid >> 5, lane = tid & 31;
    size_t frame = (size_t)blockIdx.x * 8 + wid;
    const float4* rp = (const float4*)(gc + frame * FILT);
    float4 v0 = rp[lane], v1 = rp[lane + 32];
    int ca = lane * 4, cb = 128 + lane * 4;

    float x[8];
    x[0] = fmaxf(v0.x + sB[ca], 0.f);     x[1] = fmaxf(v0.y + sB[ca + 1], 0.f);
    x[2] = fmaxf(v0.z + sB[ca + 2], 0.f); x[3] = fmaxf(v0.w + sB[ca + 3], 0.f);
    x[4] = fmaxf(v1.x + sB[cb], 0.f);     x[5] = fmaxf(v1.y + sB[cb + 1], 0.f);
    x[6] = fmaxf(v1.z + sB[cb + 2], 0.f); x[7] = fmaxf(v1.w + sB[cb + 3], 0.f);

    float s = 0.f, q = 0.f;
#pragma unroll
    for (int j = 0; j < 8; j++) { s += x[j]; q += x[j] * x[j]; }
#pragma unroll
    for (int off = 16; off > 0; off >>= 1) {
        s += __shfl_xor_sync(0xffffffffu, s, off);
        q += __shfl_xor_sync(0xffffffffu, q, off);
    }
    float m = s * (1.f / FILT);
    float rs = rsqrtf(q * (1.f / FILT) - m * m + 1e-5f);

    float y[8];
#pragma unroll
    for (int j = 0; j < 4; j++) y[j] = (x[j] - m) * rs * sG[ca + j] + sE[ca + j];
#pragma unroll
    for (int j = 0; j < 4; j++) y[4 + j] = (x[4 + j] - m) * rs * sG[cb + j] + sE[cb + j];

    if (MODE == 1) {
        float4* wp = (float4*)(outf + frame * FILT);
        wp[lane] = make_float4(y[0], y[1], y[2], y[3]);
        wp[lane + 32] = make_float4(y[4], y[5], y[6], y[7]);
    } else {
        uint2* hp = (uint2*)(outh + frame * FILT);
        uint2* mp = (uint2*)(outm + frame * FILT);
        hp[lane]      = make_uint2(pack_hi2(y[0], y[1]), pack_hi2(y[2], y[3]));
        hp[lane + 32] = make_uint2(pack_hi2(y[4], y[5]), pack_hi2(y[6], y[7]));
        mp[lane]      = make_uint2(pack_mid2(y[0], y[1]), pack_mid2(y[2], y[3]));
        mp[lane + 32] = make_uint2(pack_mid2(y[4], y[5]), pack_mid2(y[6], y[7]));
    }
}

// ---------------- pooling / mlp / expand --------------------------------------------
__global__ void phone_pool_kernel(const int* __restrict__ dur) {
    int b = blockIdx.y, p = blockIdx.x, c = threadIdx.x;
    int start = p ? g_pcum[b * PP + p - 1] : 0;
    int end = g_pcum[b * PP + p];
    if (start > TT) start = TT;
    if (end > TT) end = TT;
    float s = 0.f;
    for (int t = start; t < end; t++) s += g_x2[((size_t)(b * TT + t)) * FILT + c];
    int d = dur[b * PP + p]; if (d < 1) d = 1;
    g_ph[((size_t)(b * PP + p)) * FILT + c] = s / (float)d;
}
__global__ void word_pool_kernel(const int* __restrict__ wpl) {
    int b = blockIdx.y, w = blockIdx.x, c = threadIdx.x;
    int start = w ? g_wcum[b * WW + w - 1] : 0;
    int end = g_wcum[b * WW + w];
    if (start > PP) start = PP;
    if (end > PP) end = PP;
    float s = 0.f;
    for (int p = start; p < end; p++) s += g_ph[((size_t)(b * PP + p)) * FILT + c];
    int d = wpl[b * WW + w]; if (d < 1) d = 1;
    g_wd[((size_t)(b * WW + w)) * FILT + c] = s / (float)d;
}
__global__ void __launch_bounds__(256) mlp_kernel(
    const float* __restrict__ w1, const float* __restrict__ b1,
    const float* __restrict__ w2, const float* __restrict__ b2)
{
    __shared__ float sh[32 * FILT];
    int b = blockIdx.y, w0 = blockIdx.x * 32, o = threadIdx.x;
    for (int idx = o; idx < 32 * FILT; idx += 256)
        sh[idx] = g_wd[((size_t)(b * WW + w0)) * FILT + idx];
    __syncthreads();
    float acc[32];
    float bv = b1[o];
#pragma unroll
    for (int m = 0; m < 32; m++) acc[m] = bv;
    for (int i = 0; i < FILT; i++) {
        float wv = w1[i * FILT + o];
#pragma unroll
        for (int m = 0; m < 32; m++) acc[m] += sh[m * FILT + i] * wv;
    }
    __syncthreads();
#pragma unroll
    for (int m = 0; m < 32; m++) sh[m * FILT + o] = fmaxf(acc[m], 0.f);
    __syncthreads();
    int oo = o & (PDIM - 1);
    int mg = o >> 6;
    for (int m = mg * 8; m < mg * 8 + 8; m++) {
        float a = b2[oo];
        for (int i = 0; i < FILT; i++) a += sh[m * FILT + i] * w2[i * PDIM + oo];
        g_z[((size_t)(b * WW + w0 + m)) * PDIM + oo] = fmaxf(a, 0.f);
    }
}
__global__ void expand_kernel(const unsigned char* __restrict__ mask, float* __restrict__ out) {
    int b = blockIdx.y, p = blockIdx.x, o = threadIdx.x;
    const int* wc = g_wcum + b * WW;
    int lo = 0, hi = WW;
    while (lo < hi) { int mid = (lo + hi) >> 1; if (wc[mid] <= p) lo = mid + 1; else hi = mid; }
    int wid = lo; if (wid > WW - 1) wid = WW - 1;
    float v = g_z[((size_t)(b * WW + wid)) * PDIM + o];
    if (mask[b * PP + p]) v = 0.f;
    out[((size_t)(b * PP + p)) * PDIM + o] = v;
}

// ---------------- host launch -------------------------------------------------------
extern "C" void kernel_launch(void* const* d_in, const int* in_sizes, int n_in,
                              void* d_out, int out_size)
{
    const unsigned char* mask = (const unsigned char*)d_in[0];
    const float* mels = (const float*)d_in[1];
    const int* durations = (const int*)d_in[3];
    const int* wpl = (const int*)d_in[4];
    const float* c1w = (const float*)d_in[5];
    const float* c1b = (const float*)d_in[6];
    const float* l1g = (const float*)d_in[7];
    const float* l1b = (const float*)d_in[8];
    const float* c2w = (const float*)d_in[9];
    const float* c2b = (const float*)d_in[10];
    const float* l2g = (const float*)d_in[11];
    const float* l2b = (const float*)d_in[12];
    const float* w1 = (const float*)d_in[13];
    const float* b1 = (const float*)d_in[14];
    const float* w2 = (const float*)d_in[15];
    const float* b2 = (const float*)d_in[16];
    float* out = (float*)d_out;

    void *p_melhi, *p_melmid, *p_x1hi, *p_x1mid, *p_craw, *p_x2, *p_w1h, *p_w2h;
    cudaGetSymbolAddress(&p_melhi, g_melhi);
    cudaGetSymbolAddress(&p_melmid, g_melmid);
    cudaGetSymbolAddress(&p_x1hi, g_x1hi);
    cudaGetSymbolAddress(&p_x1mid, g_x1mid);
    cudaGetSymbolAddress(&p_craw, g_craw);
    cudaGetSymbolAddress(&p_x2, g_x2);
    cudaGetSymbolAddress(&p_w1h, g_w1h);
    cudaGetSymbolAddress(&p_w2h, g_w2h);

    cudaFuncSetAttribute(conv_mma<3, NMEL>, cudaFuncAttributeMaxDynamicSharedMemorySize, CONV_SMEM);
    cudaFuncSetAttribute(conv_mma<8, FILT>, cudaFuncAttributeMaxDynamicSharedMemorySize, CONV_SMEM);

    mel_split_kernel<<<(int)(((size_t)BB * TT * 96 + 255) / 256), 256>>>(mels);
    wsplit_kernel<NMEL, 96><<<(KK * FILT * 96 + 255) / 256, 256>>>(c1w, (__half*)p_w1h);
    wsplit_kernel<FILT, FILT><<<(KK * FILT * FILT + 255) / 256, 256>>>(c2w, (__half*)p_w2h);
    scan_kernel<<<BB, 32>>>(durations, wpl);

    dim3 cgrid(TT / 128, 2, BB);
    conv_mma<3, NMEL><<<cgrid, 256, CONV_SMEM>>>(
        (const __half*)p_melhi, (const __half*)p_melmid,
        (const __half*)p_w1h, (float*)p_craw);
    ln_kernel<0><<<BB * TT / 8, 256>>>((const float*)p_craw, c1b, l1g, l1b,
        nullptr, (__half*)p_x1hi, (__half*)p_x1mid);
    conv_mma<8, FILT><<<cgrid, 256, CONV_SMEM>>>(
        (const __half*)p_x1hi, (const __half*)p_x1mid,
        (const __half*)p_w2h, (float*)p_craw);
    ln_kernel<1><<<BB * TT / 8, 256>>>((const float*)p_craw, c2b, l2g, l2b,
        (float*)p_x2, nullptr, nullptr);

    phone_pool_kernel<<<dim3(PP, BB), FILT>>>(durations);
    word_pool_kernel<<<dim3(WW, BB), FILT>>>(wpl);
    mlp_kernel<<<dim3(WW / 32, BB), 256>>>(w1, b1, w2, b2);
    expand_kernel<<<dim3(PP, BB), PDIM>>>(mask, out);
}

// round 11
// speedup vs baseline: 1.4231x; 1.2795x over previous
#include <cuda_runtime.h>
#include <cuda_fp16.h>
#include <cstdint>

#define BB 32
#define TT 4096
#define PP 512
#define WW 128
#define NMEL 80
#define FILT 256
#define PDIM 64
#define KK 9
#define PAD 4

#define STR 40                        // smem row stride (fp16), conflict-free
#define A_ROWS 136                    // 128 + 2*PAD halo
#define A_CP 5440                     // A_ROWS*STR elems
#define B_CP 5120                     // 128*STR elems
#define OFF_B (2 * A_CP)              // 10880: A = 2 chunkbufs (hi only)
#define CONV_SMEM 65536               // max(mainloop 52480, epilogue staging 64KB)

// ---------------- device scratch ----------------------------------------------------
__device__ __half g_melhi[(size_t)BB * TT * 96];
__device__ __half g_x1hi[(size_t)BB * TT * FILT];
__device__ float g_craw[(size_t)BB * TT * FILT];
__device__ __half g_w1h[KK * FILT * 96];
__device__ __half g_w2h[KK * FILT * FILT];
__device__ float g_ph[(size_t)BB * PP * FILT];
__device__ float g_wd[(size_t)BB * WW * FILT];
__device__ float g_z [(size_t)BB * WW * PDIM];
__device__ int   g_pcum[BB * PP];
__device__ int   g_wcum[BB * WW];

// ---------------- helpers ------------------------------------------------------------
__device__ __forceinline__ uint32_t smem_u32(const void* p) {
    return (uint32_t)__cvta_generic_to_shared(p);
}
#define CP16(dst_u32, src_ptr) \
    asm volatile("cp.async.cg.shared.global [%0], [%1], 16;" :: "r"(dst_u32), "l"(src_ptr) : "memory")
#define CP_COMMIT() asm volatile("cp.async.commit_group;" ::: "memory")
#define CP_WAIT0()  asm volatile("cp.async.wait_group 0;" ::: "memory")
#define CP_WAIT1()  asm volatile("cp.async.wait_group 1;" ::: "memory")

#define MMA_F16(d, a, b) \
    asm volatile("mma.sync.aligned.m16n8k16.row.col.f32.f16.f16.f32 " \
        "{%0,%1,%2,%3},{%4,%5,%6,%7},{%8,%9},{%0,%1,%2,%3};" \
        : "+f"((d)[0]), "+f"((d)[1]), "+f"((d)[2]), "+f"((d)[3]) \
        : "r"((a)[0]), "r"((a)[1]), "r"((a)[2]), "r"((a)[3]), "r"((b)[0]), "r"((b)[1]))

#define LDM4(r0, r1, r2, r3, addr) \
    asm volatile("ldmatrix.sync.aligned.m8n8.x4.shared.b16 {%0,%1,%2,%3}, [%4];" \
        : "=r"(r0), "=r"(r1), "=r"(r2), "=r"(r3) : "r"(addr))

__device__ __forceinline__ uint32_t pack_hi2(float x0, float x1) {
    __half2 t(__float2half_rn(x0), __float2half_rn(x1));
    return *reinterpret_cast<uint32_t*>(&t);
}

// ---------------- prep kernels -------------------------------------------------------
__global__ void mel_split_kernel(const float* __restrict__ mels) {
    size_t i = (size_t)blockIdx.x * blockDim.x + threadIdx.x;
    if (i < (size_t)BB * TT * 96) {
        size_t t = i / 96;
        int ci = (int)(i % 96);
        float x = (ci < NMEL) ? mels[t * NMEL + ci] : 0.f;
        g_melhi[i] = __float2half_rn(x);
    }
}
template <int CIN, int CINP>
__global__ void wsplit_kernel(const float* __restrict__ w, __half* __restrict__ wh) {
    int i = blockIdx.x * blockDim.x + threadIdx.x;      // [tap][co][ci-padded]
    if (i < KK * FILT * CINP) {
        int ci = i % CINP;
        int co = (i / CINP) % FILT;
        int tap = i / (CINP * FILT);
        float x = (ci < CIN) ? w[(co * CIN + ci) * KK + tap] : 0.f;
        wh[i] = __float2half_rn(x);
    }
}
__global__ void scan_kernel(const int* __restrict__ dur, const int* __restrict__ wpl) {
    int b = blockIdx.x, lane = threadIdx.x;             // 32 threads/block
    int v[16], s = 0;
#pragma unroll
    for (int i = 0; i < 16; i++) { v[i] = dur[b * PP + lane * 16 + i]; s += v[i]; }
    int inc = s;
#pragma unroll
    for (int off = 1; off < 32; off <<= 1) {
        int t = __shfl_up_sync(0xffffffffu, inc, off);
        if (lane >= off) inc += t;
    }
    int base = inc - s, run = 0;
#pragma unroll
    for (int i = 0; i < 16; i++) { run += v[i]; g_pcum[b * PP + lane * 16 + i] = base + run; }
    int w[4]; s = 0;
#pragma unroll
    for (int i = 0; i < 4; i++) { w[i] = wpl[b * WW + lane * 4 + i]; s += w[i]; }
    inc = s;
#pragma unroll
    for (int off = 1; off < 32; off <<= 1) {
        int t = __shfl_up_sync(0xffffffffu, inc, off);
        if (lane >= off) inc += t;
    }
    base = inc - s; run = 0;
#pragma unroll
    for (int i = 0; i < 4; i++) { run += w[i]; g_wcum[b * WW + lane * 4 + i] = base + run; }
}

// ---------------- conv via single-term fp16 mma.sync, halo-resident A ---------------
// CIN = true input channels; chunks of 32 with a possible 16-wide tail (conv1: 80).
template <int NCH, int CIN>
__global__ void __launch_bounds__(256, 2) conv_mma(
    const __half* __restrict__ Ahi,
    const __half* __restrict__ Bh16,
    float* __restrict__ outc)
{
    constexpr int CINP = NCH * 32;
    constexpr int NST = NCH * KK;
    extern __shared__ __half smhf[];

    const int tid = threadIdx.x;
    const int wid = tid >> 5, lane = tid & 31;
    const int wm = wid & 1, wn = wid >> 1;              // 2m x 4n warps
    const int t0 = blockIdx.x * 128;
    const int n0 = blockIdx.y * 128;
    const size_t bT = (size_t)blockIdx.z * TT;
    const uint32_t smb = smem_u32(smhf);

    float acc[4][4][4];
#pragma unroll
    for (int mt = 0; mt < 4; mt++)
#pragma unroll
        for (int nt = 0; nt < 4; nt++)
#pragma unroll
            for (int q = 0; q < 4; q++) acc[mt][nt][q] = 0.f;

    // ldmatrix lane offsets
    const int a_l = ((lane >> 3) & 1) * 8 + (lane & 7);
    const int a_k = (lane >> 4) * 8;
    const int b_l = (lane >> 4) * 8 + (lane & 7);
    const int b_k = ((lane >> 3) & 1) * 8;
    uint32_t aoff[4], boff[2];
#pragma unroll
    for (int mt = 0; mt < 4; mt++)
        aoff[mt] = ((wm * 64 + mt * 16 + a_l) * STR + a_k) * 2;
#pragma unroll
    for (int np = 0; np < 2; np++)
        boff[np] = ((wn * 32 + np * 16 + b_l) * STR + b_k) * 2;

    auto issue_loads = [&](int s) {
        int chunk = s / KK, tap = s - chunk * KK;
        int kc = CIN - chunk * 32; if (kc > 32) kc = 32;     // 16-wide tail chunk
        __half* sB = smhf + OFF_B + (s % 3) * B_CP;
#pragma unroll
        for (int j = 0; j < 2; j++) {
            int q = tid + j * 256;                      // 0..511
            int row = q >> 2, c16 = q & 3;
            if (c16 * 8 < kc) {
                const __half* src = Bh16
                    + ((size_t)tap * FILT + n0 + row) * CINP + chunk * 32 + c16 * 8;
                CP16(smem_u32(sB + row * STR + c16 * 8), src);
            }
        }
        if (tap == 0) {
            __half* sA = smhf + (chunk & 1) * A_CP;
#pragma unroll
            for (int j = 0; j < 3; j++) {
                int q = tid + j * 256;
                if (q < 4 * A_ROWS) {                   // 544
                    int row = q >> 2, c16 = q & 3;
                    if (c16 * 8 >= kc) continue;
                    int trow = t0 + row - PAD;
                    __half* dst = sA + row * STR + c16 * 8;
                    if (trow >= 0 && trow < TT) {
                        const __half* src = Ahi
                            + (bT + trow) * CINP + chunk * 32 + c16 * 8;
                        CP16(smem_u32(dst), src);
                    } else {
                        *(uint4*)dst = make_uint4(0, 0, 0, 0);
                    }
                }
            }
        }
    };

    issue_loads(0); CP_COMMIT();
    issue_loads(1); CP_COMMIT();

    for (int s = 0; s < NST; s++) {
        if (s + 1 < NST) CP_WAIT1(); else CP_WAIT0();
        __syncthreads();
        if (s + 2 < NST) { issue_loads(s + 2); CP_COMMIT(); }

        int chunk = s / KK, tap = s - chunk * KK;
        uint32_t aAh = smb + (chunk & 1) * (A_CP * 2) + tap * (STR * 2);
        uint32_t aBh = smb + (OFF_B + (s % 3) * B_CP) * 2;

        auto do_kk = [&](int kk) {
            uint32_t ah[4][4], bh[4][2];
#pragma unroll
            for (int mt = 0; mt < 4; mt++)
                LDM4(ah[mt][0], ah[mt][1], ah[mt][2], ah[mt][3], aAh + aoff[mt] + kk * 32);
#pragma unroll
            for (int np = 0; np < 2; np++)
                LDM4(bh[2 * np][0], bh[2 * np][1], bh[2 * np + 1][0], bh[2 * np + 1][1],
                     aBh + boff[np] + kk * 32);
#pragma unroll
            for (int mt = 0; mt < 4; mt++)
#pragma unroll
                for (int nt = 0; nt < 4; nt++) MMA_F16(acc[mt][nt], ah[mt], bh[nt]);
        };

        do_kk(0);
        if ((CIN - chunk * 32) >= 32) do_kk(1);         // tail chunk has only k16
    }
    __syncthreads();

    // ---------------- epilogue: stage to smem, coalesced store ----------------------
    float* st = (float*)smhf;                 // 64 KB staging
    const int r = lane >> 2, cq = lane & 3;
#pragma unroll
    for (int mt = 0; mt < 4; mt++) {
        int R0 = wm * 64 + mt * 16 + r;
#pragma unroll
        for (int nt = 0; nt < 4; nt++) {
            int C = wn * 32 + nt * 8 + 2 * cq;
            st[R0 * 128 + C]           = acc[mt][nt][0];
            st[R0 * 128 + C + 1]       = acc[mt][nt][1];
            st[(R0 + 8) * 128 + C]     = acc[mt][nt][2];
            st[(R0 + 8) * 128 + C + 1] = acc[mt][nt][3];
        }
    }
    __syncthreads();
#pragma unroll
    for (int i = 0; i < 16; i++) {
        int f4 = tid + i * 256;               // 4096 float4 = 128x128
        int row = f4 >> 5, c4 = f4 & 31;
        *(float4*)(outc + (bT + t0 + row) * FILT + n0 + c4 * 4) = ((float4*)st)[f4];
    }
}

// ---------------- bias + relu + LN pass (warp per frame) -> fp16 hi -----------------
__global__ void __launch_bounds__(256) ln_hi_kernel(
    const float* __restrict__ gc,
    const float* __restrict__ bias, const float* __restrict__ gamma,
    const float* __restrict__ beta,
    __half* __restrict__ outh)
{
    __shared__ float sB[FILT], sG[FILT], sE[FILT];
    int tid = threadIdx.x;
    if (tid < FILT) { sB[tid] = bias[tid]; sG[tid] = gamma[tid]; sE[tid] = beta[tid]; }
    __syncthreads();

    int wid = tid >> 5, lane = tid & 31;
    size_t frame = (size_t)blockIdx.x * 8 + wid;
    const float4* rp = (const float4*)(gc + frame * FILT);
    float4 v0 = rp[lane], v1 = rp[lane + 32];
    int ca = lane * 4, cb = 128 + lane * 4;

    float x[8];
    x[0] = fmaxf(v0.x + sB[ca], 0.f);     x[1] = fmaxf(v0.y + sB[ca + 1], 0.f);
    x[2] = fmaxf(v0.z + sB[ca + 2], 0.f); x[3] = fmaxf(v0.w + sB[ca + 3], 0.f);
    x[4] = fmaxf(v1.x + sB[cb], 0.f);     x[5] = fmaxf(v1.y + sB[cb + 1], 0.f);
    x[6] = fmaxf(v1.z + sB[cb + 2], 0.f); x[7] = fmaxf(v1.w + sB[cb + 3], 0.f);

    float s = 0.f, q = 0.f;
#pragma unroll
    for (int j = 0; j < 8; j++) { s += x[j]; q += x[j] * x[j]; }
#pragma unroll
    for (int off = 16; off > 0; off >>= 1) {
        s += __shfl_xor_sync(0xffffffffu, s, off);
        q += __shfl_xor_sync(0xffffffffu, q, off);
    }
    float m = s * (1.f / FILT);
    float rs = rsqrtf(q * (1.f / FILT) - m * m + 1e-5f);

    float y[8];
#pragma unroll
    for (int j = 0; j < 4; j++) y[j] = (x[j] - m) * rs * sG[ca + j] + sE[ca + j];
#pragma unroll
    for (int j = 0; j < 4; j++) y[4 + j] = (x[4 + j] - m) * rs * sG[cb + j] + sE[cb + j];

    uint2* hp = (uint2*)(outh + frame * FILT);
    hp[lane]      = make_uint2(pack_hi2(y[0], y[1]), pack_hi2(y[2], y[3]));
    hp[lane + 32] = make_uint2(pack_hi2(y[4], y[5]), pack_hi2(y[6], y[7]));
}

// ---------------- fused bias+relu+LN + phone mean pool ------------------------------
// block 256 threads = one phone; loops over its frames, LN on the fly, accumulates.
__global__ void __launch_bounds__(256) lnpool_kernel(
    const int* __restrict__ dur, const float* __restrict__ gc,
    const float* __restrict__ bias, const float* __restrict__ gamma,
    const float* __restrict__ beta)
{
    __shared__ float sB[FILT], sG[FILT], sE[FILT];
    __shared__ float red[16];
    int b = blockIdx.y, p = blockIdx.x, c = threadIdx.x;
    int wid = c >> 5, lane = c & 31;
    sB[c] = bias[c]; sG[c] = gamma[c]; sE[c] = beta[c];
    __syncthreads();

    int start = p ? g_pcum[b * PP + p - 1] : 0;
    int end = g_pcum[b * PP + p];
    if (start > TT) start = TT;
    if (end > TT) end = TT;

    float accum = 0.f;
    for (int t = start; t < end; t++) {
        float v = fmaxf(gc[((size_t)(b * TT + t)) * FILT + c] + sB[c], 0.f);
        float s = v, q = v * v;
#pragma unroll
        for (int off = 16; off > 0; off >>= 1) {
            s += __shfl_xor_sync(0xffffffffu, s, off);
            q += __shfl_xor_sync(0xffffffffu, q, off);
        }
        if (lane == 0) { red[wid] = s; red[8 + wid] = q; }
        __syncthreads();
        s = red[0] + red[1] + red[2] + red[3] + red[4] + red[5] + red[6] + red[7];
        q = red[8] + red[9] + red[10] + red[11] + red[12] + red[13] + red[14] + red[15];
        float m = s * (1.f / FILT);
        float rs = rsqrtf(q * (1.f / FILT) - m * m + 1e-5f);
        accum += (v - m) * rs * sG[c] + sE[c];
        __syncthreads();
    }
    int d = dur[b * PP + p]; if (d < 1) d = 1;
    g_ph[((size_t)(b * PP + p)) * FILT + c] = accum / (float)d;
}

// ---------------- word pool / mlp / expand ------------------------------------------
__global__ void word_pool_kernel(const int* __restrict__ wpl) {
    int b = blockIdx.y, w = blockIdx.x, c = threadIdx.x;
    int start = w ? g_wcum[b * WW + w - 1] : 0;
    int end = g_wcum[b * WW + w];
    if (start > PP) start = PP;
    if (end > PP) end = PP;
    float s = 0.f;
    for (int p = start; p < end; p++) s += g_ph[((size_t)(b * PP + p)) * FILT + c];
    int d = wpl[b * WW + w]; if (d < 1) d = 1;
    g_wd[((size_t)(b * WW + w)) * FILT + c] = s / (float)d;
}
__global__ void __launch_bounds__(256) mlp_kernel(
    const float* __restrict__ w1, const float* __restrict__ b1,
    const float* __restrict__ w2, const float* __restrict__ b2)
{
    __shared__ float sh[32 * FILT];
    int b = blockIdx.y, w0 = blockIdx.x * 32, o = threadIdx.x;
    for (int idx = o; idx < 32 * FILT; idx += 256)
        sh[idx] = g_wd[((size_t)(b * WW + w0)) * FILT + idx];
    __syncthreads();
    float acc[32];
    float bv = b1[o];
#pragma unroll
    for (int m = 0; m < 32; m++) acc[m] = bv;
    for (int i = 0; i < FILT; i++) {
        float wv = w1[i * FILT + o];
#pragma unroll
        for (int m = 0; m < 32; m++) acc[m] += sh[m * FILT + i] * wv;
    }
    __syncthreads();
#pragma unroll
    for (int m = 0; m < 32; m++) sh[m * FILT + o] = fmaxf(acc[m], 0.f);
    __syncthreads();
    int oo = o & (PDIM - 1);
    int mg = o >> 6;
    for (int m = mg * 8; m < mg * 8 + 8; m++) {
        float a = b2[oo];
        for (int i = 0; i < FILT; i++) a += sh[m * FILT + i] * w2[i * PDIM + oo];
        g_z[((size_t)(b * WW + w0 + m)) * PDIM + oo] = fmaxf(a, 0.f);
    }
}
__global__ void expand_kernel(const unsigned char* __restrict__ mask, float* __restrict__ out) {
    int b = blockIdx.y, p = blockIdx.x, o = threadIdx.x;
    const int* wc = g_wcum + b * WW;
    int lo = 0, hi = WW;
    while (lo < hi) { int mid = (lo + hi) >> 1; if (wc[mid] <= p) lo = mid + 1; else hi = mid; }
    int wid = lo; if (wid > WW - 1) wid = WW - 1;
    float v = g_z[((size_t)(b * WW + wid)) * PDIM + o];
    if (mask[b * PP + p]) v = 0.f;
    out[((size_t)(b * PP + p)) * PDIM + o] = v;
}

// ---------------- host launch -------------------------------------------------------
extern "C" void kernel_launch(void* const* d_in, const int* in_sizes, int n_in,
                              void* d_out, int out_size)
{
    const unsigned char* mask = (const unsigned char*)d_in[0];
    const float* mels = (const float*)d_in[1];
    const int* durations = (const int*)d_in[3];
    const int* wpl = (const int*)d_in[4];
    const float* c1w = (const float*)d_in[5];
    const float* c1b = (const float*)d_in[6];
    const float* l1g = (const float*)d_in[7];
    const float* l1b = (const float*)d_in[8];
    const float* c2w = (const float*)d_in[9];
    const float* c2b = (const float*)d_in[10];
    const float* l2g = (const float*)d_in[11];
    const float* l2b = (const float*)d_in[12];
    const float* w1 = (const float*)d_in[13];
    const float* b1 = (const float*)d_in[14];
    const float* w2 = (const float*)d_in[15];
    const float* b2 = (const float*)d_in[16];
    float* out = (float*)d_out;

    void *p_melhi, *p_x1hi, *p_craw, *p_w1h, *p_w2h;
    cudaGetSymbolAddress(&p_melhi, g_melhi);
    cudaGetSymbolAddress(&p_x1hi, g_x1hi);
    cudaGetSymbolAddress(&p_craw, g_craw);
    cudaGetSymbolAddress(&p_w1h, g_w1h);
    cudaGetSymbolAddress(&p_w2h, g_w2h);

    cudaFuncSetAttribute(conv_mma<3, NMEL>, cudaFuncAttributeMaxDynamicSharedMemorySize, CONV_SMEM);
    cudaFuncSetAttribute(conv_mma<8, FILT>, cudaFuncAttributeMaxDynamicSharedMemorySize, CONV_SMEM);

    mel_split_kernel<<<(int)(((size_t)BB * TT * 96 + 255) / 256), 256>>>(mels);
    wsplit_kernel<NMEL, 96><<<(KK * FILT * 96 + 255) / 256, 256>>>(c1w, (__half*)p_w1h);
    wsplit_kernel<FILT, FILT><<<(KK * FILT * FILT + 255) / 256, 256>>>(c2w, (__half*)p_w2h);
    scan_kernel<<<BB, 32>>>(durations, wpl);

    dim3 cgrid(TT / 128, 2, BB);
    conv_mma<3, NMEL><<<cgrid, 256, CONV_SMEM>>>(
        (const __half*)p_melhi, (const __half*)p_w1h, (float*)p_craw);
    ln_hi_kernel<<<BB * TT / 8, 256>>>((const float*)p_craw, c1b, l1g, l1b,
        (__half*)p_x1hi);
    conv_mma<8, FILT><<<cgrid, 256, CONV_SMEM>>>(
        (const __half*)p_x1hi, (const __half*)p_w2h, (float*)p_craw);

    lnpool_kernel<<<dim3(PP, BB), FILT>>>(durations, (const float*)p_craw,
        c2b, l2g, l2b);
    word_pool_kernel<<<dim3(WW, BB), FILT>>>(wpl);
    mlp_kernel<<<dim3(WW / 32, BB), 256>>>(w1, b1, w2, b2);
    expand_kernel<<<dim3(PP, BB), PDIM>>>(mask, out);
}

// round 12
// speedup vs baseline: 1.4634x; 1.0283x over previous
#include <cuda_runtime.h>
#include <cuda_fp16.h>
#include <cstdint>

#define BB 32
#define TT 4096
#define PP 512
#define WW 128
#define NMEL 80
#define FILT 256
#define PDIM 64
#define KK 9
#define PAD 4

// ---- conv2 (M=128 x N=128) ----
#define STR 40
#define A_ROWS 136
#define A_CP 5440
#define B_CP 5120
#define OFF_B (2 * A_CP)              // 10880 elems
#define CONV2_SMEM ((OFF_B + 6 * B_CP) * 2)   // 83200 B -> 2 CTAs/SM

// ---- conv1 fused (M=64 x N=256) ----
#define C1_AROWS 72
#define C1_ACP (C1_AROWS * STR)       // 2880 elems
#define C1_BCP (FILT * STR)           // 10240 elems
#define C1_OFFB (2 * C1_ACP)          // 5760 elems
#define CONV1_SMEM ((C1_OFFB + 3 * C1_BCP) * 2)  // 72960 B -> 2 CTAs/SM

// ---------------- device scratch ----------------------------------------------------
__device__ __half g_melhi[(size_t)BB * TT * 96];
__device__ __half g_x1hi[(size_t)BB * TT * FILT];
__device__ float g_craw[(size_t)BB * TT * FILT];
__device__ __half g_w1h[KK * FILT * 96];
__device__ __half g_w2h[KK * FILT * FILT];
__device__ float g_ph[(size_t)BB * PP * FILT];
__device__ float g_wd[(size_t)BB * WW * FILT];
__device__ float g_z [(size_t)BB * WW * PDIM];
__device__ int   g_pcum[BB * PP];
__device__ int   g_wcum[BB * WW];

// ---------------- helpers ------------------------------------------------------------
__device__ __forceinline__ uint32_t smem_u32(const void* p) {
    return (uint32_t)__cvta_generic_to_shared(p);
}
#define CP16(dst_u32, src_ptr) \
    asm volatile("cp.async.cg.shared.global [%0], [%1], 16;" :: "r"(dst_u32), "l"(src_ptr) : "memory")
#define CP_COMMIT() asm volatile("cp.async.commit_group;" ::: "memory")
#define CP_WAIT0()  asm volatile("cp.async.wait_group 0;" ::: "memory")
#define CP_WAIT1()  asm volatile("cp.async.wait_group 1;" ::: "memory")
#define CP_WAIT2()  asm volatile("cp.async.wait_group 2;" ::: "memory")
#define CP_WAIT4()  asm volatile("cp.async.wait_group 4;" ::: "memory")

#define MMA_F16(d, a, b) \
    asm volatile("mma.sync.aligned.m16n8k16.row.col.f32.f16.f16.f32 " \
        "{%0,%1,%2,%3},{%4,%5,%6,%7},{%8,%9},{%0,%1,%2,%3};" \
        : "+f"((d)[0]), "+f"((d)[1]), "+f"((d)[2]), "+f"((d)[3]) \
        : "r"((a)[0]), "r"((a)[1]), "r"((a)[2]), "r"((a)[3]), "r"((b)[0]), "r"((b)[1]))

#define LDM4(r0, r1, r2, r3, addr) \
    asm volatile("ldmatrix.sync.aligned.m8n8.x4.shared.b16 {%0,%1,%2,%3}, [%4];" \
        : "=r"(r0), "=r"(r1), "=r"(r2), "=r"(r3) : "r"(addr))

__device__ __forceinline__ uint32_t pack_hi2(float x0, float x1) {
    __half2 t(__float2half_rn(x0), __float2half_rn(x1));
    return *reinterpret_cast<uint32_t*>(&t);
}

// ---------------- prep kernels -------------------------------------------------------
__global__ void mel_split_kernel(const float* __restrict__ mels) {
    size_t i = (size_t)blockIdx.x * blockDim.x + threadIdx.x;
    if (i < (size_t)BB * TT * 96) {
        size_t t = i / 96;
        int ci = (int)(i % 96);
        float x = (ci < NMEL) ? mels[t * NMEL + ci] : 0.f;
        g_melhi[i] = __float2half_rn(x);
    }
}
template <int CIN, int CINP>
__global__ void wsplit_kernel(const float* __restrict__ w, __half* __restrict__ wh) {
    int i = blockIdx.x * blockDim.x + threadIdx.x;      // [tap][co][ci-padded]
    if (i < KK * FILT * CINP) {
        int ci = i % CINP;
        int co = (i / CINP) % FILT;
        int tap = i / (CINP * FILT);
        float x = (ci < CIN) ? w[(co * CIN + ci) * KK + tap] : 0.f;
        wh[i] = __float2half_rn(x);
    }
}
__global__ void scan_kernel(const int* __restrict__ dur, const int* __restrict__ wpl) {
    int b = blockIdx.x, lane = threadIdx.x;
    int v[16], s = 0;
#pragma unroll
    for (int i = 0; i < 16; i++) { v[i] = dur[b * PP + lane * 16 + i]; s += v[i]; }
    int inc = s;
#pragma unroll
    for (int off = 1; off < 32; off <<= 1) {
        int t = __shfl_up_sync(0xffffffffu, inc, off);
        if (lane >= off) inc += t;
    }
    int base = inc - s, run = 0;
#pragma unroll
    for (int i = 0; i < 16; i++) { run += v[i]; g_pcum[b * PP + lane * 16 + i] = base + run; }
    int w[4]; s = 0;
#pragma unroll
    for (int i = 0; i < 4; i++) { w[i] = wpl[b * WW + lane * 4 + i]; s += w[i]; }
    inc = s;
#pragma unroll
    for (int off = 1; off < 32; off <<= 1) {
        int t = __shfl_up_sync(0xffffffffu, inc, off);
        if (lane >= off) inc += t;
    }
    base = inc - s; run = 0;
#pragma unroll
    for (int i = 0; i < 4; i++) { run += w[i]; g_wcum[b * WW + lane * 4 + i] = base + run; }
}

// ---------------- conv1 fused: fp16 mma + bias + relu + LN -> fp16 hi ----------------
// M=64 x N=256 per CTA, 8 warps (2m x 4n), 2 CTAs/SM. CIN=80 padded to 96.
__global__ void __launch_bounds__(256, 2) conv1_fused(
    const __half* __restrict__ Ahi, const __half* __restrict__ Bh16,
    const float* __restrict__ bias, const float* __restrict__ gamma,
    const float* __restrict__ beta, __half* __restrict__ outh)
{
    constexpr int CIN = NMEL, CINP = 96, NST = 3 * KK;
    extern __shared__ __half smhf[];
    __shared__ float sB[FILT], sG[FILT], sE[FILT];
    __shared__ float s_m[64], s_r[64];

    const int tid = threadIdx.x;
    const int wid = tid >> 5, lane = tid & 31;
    const int wm = wid & 1, wn = wid >> 1;
    const int t0 = blockIdx.x * 64;
    const size_t bT = (size_t)blockIdx.y * TT;
    const uint32_t smb = smem_u32(smhf);

    if (tid < FILT) { sB[tid] = bias[tid]; sG[tid] = gamma[tid]; sE[tid] = beta[tid]; }

    float acc[2][8][4];
#pragma unroll
    for (int mt = 0; mt < 2; mt++)
#pragma unroll
        for (int nt = 0; nt < 8; nt++)
#pragma unroll
            for (int q = 0; q < 4; q++) acc[mt][nt][q] = 0.f;

    const int a_l = ((lane >> 3) & 1) * 8 + (lane & 7);
    const int a_k = (lane >> 4) * 8;
    const int b_l = (lane >> 4) * 8 + (lane & 7);
    const int b_k = ((lane >> 3) & 1) * 8;
    uint32_t aoff[2], boff[4];
#pragma unroll
    for (int mt = 0; mt < 2; mt++)
        aoff[mt] = ((wm * 32 + mt * 16 + a_l) * STR + a_k) * 2;
#pragma unroll
    for (int np = 0; np < 4; np++)
        boff[np] = ((wn * 64 + np * 16 + b_l) * STR + b_k) * 2;

    auto issue_loads = [&](int s) {
        int chunk = s / KK, tap = s - chunk * KK;
        int kc = CIN - chunk * 32; if (kc > 32) kc = 32;
        __half* sBp = smhf + C1_OFFB + (s % 3) * C1_BCP;
#pragma unroll
        for (int j = 0; j < 4; j++) {
            int q = tid + j * 256;                      // 256 rows x 4
            int row = q >> 2, c16 = q & 3;
            if (c16 * 8 < kc) {
                const __half* src = Bh16
                    + ((size_t)tap * FILT + row) * CINP + chunk * 32 + c16 * 8;
                CP16(smem_u32(sBp + row * STR + c16 * 8), src);
            }
        }
        if (tap == 0) {
            __half* sA = smhf + (chunk & 1) * C1_ACP;
#pragma unroll
            for (int j = 0; j < 2; j++) {
                int q = tid + j * 256;
                if (q < 4 * C1_AROWS) {                 // 288
                    int row = q >> 2, c16 = q & 3;
                    if (c16 * 8 >= kc) continue;
                    int trow = t0 + row - PAD;
                    __half* dst = sA + row * STR + c16 * 8;
                    if (trow >= 0 && trow < TT) {
                        const __half* src = Ahi
                            + (bT + trow) * CINP + chunk * 32 + c16 * 8;
                        CP16(smem_u32(dst), src);
                    } else {
                        *(uint4*)dst = make_uint4(0, 0, 0, 0);
                    }
                }
            }
        }
    };

    issue_loads(0); CP_COMMIT();
    issue_loads(1); CP_COMMIT();

    for (int s = 0; s < NST; s++) {
        if (s + 1 < NST) CP_WAIT1(); else CP_WAIT0();
        __syncthreads();
        if (s + 2 < NST) { issue_loads(s + 2); CP_COMMIT(); }

        int chunk = s / KK, tap = s - chunk * KK;
        uint32_t aAh = smb + (chunk & 1) * (C1_ACP * 2) + tap * (STR * 2);
        uint32_t aB  = smb + (C1_OFFB + (s % 3) * C1_BCP) * 2;

        auto do_kk = [&](int kk) {
            uint32_t ah[2][4], bh[8][2];
#pragma unroll
            for (int mt = 0; mt < 2; mt++)
                LDM4(ah[mt][0], ah[mt][1], ah[mt][2], ah[mt][3], aAh + aoff[mt] + kk * 32);
#pragma unroll
            for (int np = 0; np < 4; np++)
                LDM4(bh[2 * np][0], bh[2 * np][1], bh[2 * np + 1][0], bh[2 * np + 1][1],
                     aB + boff[np] + kk * 32);
#pragma unroll
            for (int mt = 0; mt < 2; mt++)
#pragma unroll
                for (int nt = 0; nt < 8; nt++) MMA_F16(acc[mt][nt], ah[mt], bh[nt]);
        };
        do_kk(0);
        if ((CIN - chunk * 32) >= 32) do_kk(1);
    }
    __syncthreads();

    // epilogue: bias+relu -> smem (64x256 fp32), LN, write fp16 hi
    float* st = (float*)smhf;
    const int r = lane >> 2, cq = lane & 3;
#pragma unroll
    for (int mt = 0; mt < 2; mt++) {
        int R0 = wm * 32 + mt * 16 + r;
#pragma unroll
        for (int nt = 0; nt < 8; nt++) {
            int C = wn * 64 + nt * 8 + 2 * cq;
            st[R0 * FILT + C]           = fmaxf(acc[mt][nt][0] + sB[C], 0.f);
            st[R0 * FILT + C + 1]       = fmaxf(acc[mt][nt][1] + sB[C + 1], 0.f);
            st[(R0 + 8) * FILT + C]     = fmaxf(acc[mt][nt][2] + sB[C], 0.f);
            st[(R0 + 8) * FILT + C + 1] = fmaxf(acc[mt][nt][3] + sB[C + 1], 0.f);
        }
    }
    __syncthreads();

#pragma unroll
    for (int rr = 0; rr < 8; rr++) {
        int row = wid * 8 + rr;
        float4 u = ((const float4*)st)[row * 64 + lane];
        float4 v = ((const float4*)st)[row * 64 + lane + 32];
        float s = u.x + u.y + u.z + u.w + v.x + v.y + v.z + v.w;
        float q = u.x * u.x + u.y * u.y + u.z * u.z + u.w * u.w
                + v.x * v.x + v.y * v.y + v.z * v.z + v.w * v.w;
#pragma unroll
        for (int off = 16; off > 0; off >>= 1) {
            s += __shfl_xor_sync(0xffffffffu, s, off);
            q += __shfl_xor_sync(0xffffffffu, q, off);
        }
        if (lane == 0) {
            float m = s * (1.f / FILT);
            s_m[row] = m;
            s_r[row] = rsqrtf(q * (1.f / FILT) - m * m + 1e-5f);
        }
    }
    __syncthreads();

#pragma unroll
    for (int j = 0; j < 16; j++) {
        int f4 = tid + j * 256;               // 4096 float4 = 64x256
        int row = f4 >> 6, c4 = f4 & 63;
        float4 v = ((const float4*)st)[f4];
        float m = s_m[row], rs = s_r[row];
        int C = c4 * 4;
        float y0 = (v.x - m) * rs * sG[C]     + sE[C];
        float y1 = (v.y - m) * rs * sG[C + 1] + sE[C + 1];
        float y2 = (v.z - m) * rs * sG[C + 2] + sE[C + 2];
        float y3 = (v.w - m) * rs * sG[C + 3] + sE[C + 3];
        size_t o = (bT + t0 + row) * FILT + C;
        *(uint2*)(outh + o) = make_uint2(pack_hi2(y0, y1), pack_hi2(y2, y3));
    }
}

// ---------------- conv2: fp16 mma, M=128 x N=128, paired-stage sync ------------------
__global__ void __launch_bounds__(256, 2) conv2_mma(
    const __half* __restrict__ Ahi, const __half* __restrict__ Bh16,
    float* __restrict__ outc)
{
    constexpr int CIN = FILT, CINP = FILT, NST = 8 * KK;   // 72, even
    extern __shared__ __half smhf[];

    const int tid = threadIdx.x;
    const int wid = tid >> 5, lane = tid & 31;
    const int wm = wid & 1, wn = wid >> 1;
    const int t0 = blockIdx.x * 128;
    const int n0 = blockIdx.y * 128;
    const size_t bT = (size_t)blockIdx.z * TT;
    const uint32_t smb = smem_u32(smhf);

    float acc[4][4][4];
#pragma unroll
    for (int mt = 0; mt < 4; mt++)
#pragma unroll
        for (int nt = 0; nt < 4; nt++)
#pragma unroll
            for (int q = 0; q < 4; q++) acc[mt][nt][q] = 0.f;

    const int a_l = ((lane >> 3) & 1) * 8 + (lane & 7);
    const int a_k = (lane >> 4) * 8;
    const int b_l = (lane >> 4) * 8 + (lane & 7);
    const int b_k = ((lane >> 3) & 1) * 8;
    uint32_t aoff[4], boff[2];
#pragma unroll
    for (int mt = 0; mt < 4; mt++)
        aoff[mt] = ((wm * 64 + mt * 16 + a_l) * STR + a_k) * 2;
#pragma unroll
    for (int np = 0; np < 2; np++)
        boff[np] = ((wn * 32 + np * 16 + b_l) * STR + b_k) * 2;

    auto issue_loads = [&](int s) {
        int chunk = s / KK, tap = s - chunk * KK;
        __half* sB = smhf + OFF_B + (s % 6) * B_CP;
#pragma unroll
        for (int j = 0; j < 2; j++) {
            int q = tid + j * 256;                      // 128 rows x 4
            int row = q >> 2, c16 = q & 3;
            const __half* src = Bh16
                + ((size_t)tap * FILT + n0 + row) * CINP + chunk * 32 + c16 * 8;
            CP16(smem_u32(sB + row * STR + c16 * 8), src);
        }
        if (tap == 0) {
            __half* sA = smhf + (chunk & 1) * A_CP;
#pragma unroll
            for (int j = 0; j < 3; j++) {
                int q = tid + j * 256;
                if (q < 4 * A_ROWS) {                   // 544
                    int row = q >> 2, c16 = q & 3;
                    int trow = t0 + row - PAD;
                    __half* dst = sA + row * STR + c16 * 8;
                    if (trow >= 0 && trow < TT) {
                        const __half* src = Ahi
                            + (bT + trow) * CINP + chunk * 32 + c16 * 8;
                        CP16(smem_u32(dst), src);
                    } else {
                        *(uint4*)dst = make_uint4(0, 0, 0, 0);
                    }
                }
            }
        }
    };

#pragma unroll
    for (int i = 0; i < 6; i++) { issue_loads(i); CP_COMMIT(); }

    auto compute_stage = [&](int s) {
        int chunk = s / KK, tap = s - chunk * KK;
        uint32_t aAh = smb + (chunk & 1) * (A_CP * 2) + tap * (STR * 2);
        uint32_t aBh = smb + (OFF_B + (s % 6) * B_CP) * 2;
#pragma unroll
        for (int kk = 0; kk < 2; kk++) {
            uint32_t ah[4][4], bh[4][2];
#pragma unroll
            for (int mt = 0; mt < 4; mt++)
                LDM4(ah[mt][0], ah[mt][1], ah[mt][2], ah[mt][3], aAh + aoff[mt] + kk * 32);
#pragma unroll
            for (int np = 0; np < 2; np++)
                LDM4(bh[2 * np][0], bh[2 * np][1], bh[2 * np + 1][0], bh[2 * np + 1][1],
                     aBh + boff[np] + kk * 32);
#pragma unroll
            for (int mt = 0; mt < 4; mt++)
#pragma unroll
                for (int nt = 0; nt < 4; nt++) MMA_F16(acc[mt][nt], ah[mt], bh[nt]);
        }
    };

    for (int p = 0; p < NST / 2; p++) {
        int s0 = 2 * p;
        int rem = NST - s0 - 2;                 // pending groups allowed after wait
        if (rem >= 4) CP_WAIT4();
        else if (rem >= 2) CP_WAIT2();
        else CP_WAIT0();
        __syncthreads();
        if (s0 + 4 < NST) { issue_loads(s0 + 4); CP_COMMIT(); }
        if (s0 + 5 < NST) { issue_loads(s0 + 5); CP_COMMIT(); }
        compute_stage(s0);
        compute_stage(s0 + 1);
    }
    __syncthreads();

    // epilogue: stage to smem, coalesced store
    float* st = (float*)smhf;                 // 64 KB staging
    const int r = lane >> 2, cq = lane & 3;
#pragma unroll
    for (int mt = 0; mt < 4; mt++) {
        int R0 = wm * 64 + mt * 16 + r;
#pragma unroll
        for (int nt = 0; nt < 4; nt++) {
            int C = wn * 32 + nt * 8 + 2 * cq;
            st[R0 * 128 + C]           = acc[mt][nt][0];
            st[R0 * 128 + C + 1]       = acc[mt][nt][1];
            st[(R0 + 8) * 128 + C]     = acc[mt][nt][2];
            st[(R0 + 8) * 128 + C + 1] = acc[mt][nt][3];
        }
    }
    __syncthreads();
#pragma unroll
    for (int i = 0; i < 16; i++) {
        int f4 = tid + i * 256;               // 4096 float4 = 128x128
        int row = f4 >> 5, c4 = f4 & 31;
        *(float4*)(outc + (bT + t0 + row) * FILT + n0 + c4 * 4) = ((float4*)st)[f4];
    }
}

// ---------------- fused bias+relu+LN + phone mean pool ------------------------------
__global__ void __launch_bounds__(256) lnpool_kernel(
    const int* __restrict__ dur, const float* __restrict__ gc,
    const float* __restrict__ bias, const float* __restrict__ gamma,
    const float* __restrict__ beta)
{
    __shared__ float sB[FILT], sG[FILT], sE[FILT];
    __shared__ float red[16];
    int b = blockIdx.y, p = blockIdx.x, c = threadIdx.x;
    int wid = c >> 5, lane = c & 31;
    sB[c] = bias[c]; sG[c] = gamma[c]; sE[c] = beta[c];
    __syncthreads();

    int start = p ? g_pcum[b * PP + p - 1] : 0;
    int end = g_pcum[b * PP + p];
    if (start > TT) start = TT;
    if (end > TT) end = TT;

    float accum = 0.f;
    for (int t = start; t < end; t++) {
        float v = fmaxf(gc[((size_t)(b * TT + t)) * FILT + c] + sB[c], 0.f);
        float s = v, q = v * v;
#pragma unroll
        for (int off = 16; off > 0; off >>= 1) {
            s += __shfl_xor_sync(0xffffffffu, s, off);
            q += __shfl_xor_sync(0xffffffffu, q, off);
        }
        if (lane == 0) { red[wid] = s; red[8 + wid] = q; }
        __syncthreads();
        s = red[0] + red[1] + red[2] + red[3] + red[4] + red[5] + red[6] + red[7];
        q = red[8] + red[9] + red[10] + red[11] + red[12] + red[13] + red[14] + red[15];
        float m = s * (1.f / FILT);
        float rs = rsqrtf(q * (1.f / FILT) - m * m + 1e-5f);
        accum += (v - m) * rs * sG[c] + sE[c];
        __syncthreads();
    }
    int d = dur[b * PP + p]; if (d < 1) d = 1;
    g_ph[((size_t)(b * PP + p)) * FILT + c] = accum / (float)d;
}

// ---------------- word pool / mlp / expand ------------------------------------------
__global__ void word_pool_kernel(const int* __restrict__ wpl) {
    int b = blockIdx.y, w = blockIdx.x, c = threadIdx.x;
    int start = w ? g_wcum[b * WW + w - 1] : 0;
    int end = g_wcum[b * WW + w];
    if (start > PP) start = PP;
    if (end > PP) end = PP;
    float s = 0.f;
    for (int p = start; p < end; p++) s += g_ph[((size_t)(b * PP + p)) * FILT + c];
    int d = wpl[b * WW + w]; if (d < 1) d = 1;
    g_wd[((size_t)(b * WW + w)) * FILT + c] = s / (float)d;
}
__global__ void __launch_bounds__(256) mlp_kernel(
    const float* __restrict__ w1, const float* __restrict__ b1,
    const float* __restrict__ w2, const float* __restrict__ b2)
{
    __shared__ float sh[32 * FILT];
    int b = blockIdx.y, w0 = blockIdx.x * 32, o = threadIdx.x;
    for (int idx = o; idx < 32 * FILT; idx += 256)
        sh[idx] = g_wd[((size_t)(b * WW + w0)) * FILT + idx];
    __syncthreads();
    float acc[32];
    float bv = b1[o];
#pragma unroll
    for (int m = 0; m < 32; m++) acc[m] = bv;
    for (int i = 0; i < FILT; i++) {
        float wv = w1[i * FILT + o];
#pragma unroll
        for (int m = 0; m < 32; m++) acc[m] += sh[m * FILT + i] * wv;
    }
    __syncthreads();
#pragma unroll
    for (int m = 0; m < 32; m++) sh[m * FILT + o] = fmaxf(acc[m], 0.f);
    __syncthreads();
    int oo = o & (PDIM - 1);
    int mg = o >> 6;
    for (int m = mg * 8; m < mg * 8 + 8; m++) {
        float a = b2[oo];
        for (int i = 0; i < FILT; i++) a += sh[m * FILT + i] * w2[i * PDIM + oo];
        g_z[((size_t)(b * WW + w0 + m)) * PDIM + oo] = fmaxf(a, 0.f);
    }
}
__global__ void expand_kernel(const unsigned char* __restrict__ mask, float* __restrict__ out) {
    int b = blockIdx.y, p = blockIdx.x, o = threadIdx.x;
    const int* wc = g_wcum + b * WW;
    int lo = 0, hi = WW;
    while (lo < hi) { int mid = (lo + hi) >> 1; if (wc[mid] <= p) lo = mid + 1; else hi = mid; }
    int wid = lo; if (wid > WW - 1) wid = WW - 1;
    float v = g_z[((size_t)(b * WW + wid)) * PDIM + o];
    if (mask[b * PP + p]) v = 0.f;
    out[((size_t)(b * PP + p)) * PDIM + o] = v;
}

// ---------------- host launch -------------------------------------------------------
extern "C" void kernel_launch(void* const* d_in, const int* in_sizes, int n_in,
                              void* d_out, int out_size)
{
    const unsigned char* mask = (const unsigned char*)d_in[0];
    const float* mels = (const float*)d_in[1];
    const int* durations = (const int*)d_in[3];
    const int* wpl = (const int*)d_in[4];
    const float* c1w = (const float*)d_in[5];
    const float* c1b = (const float*)d_in[6];
    const float* l1g = (const float*)d_in[7];
    const float* l1b = (const float*)d_in[8];
    const float* c2w = (const float*)d_in[9];
    const float* c2b = (const float*)d_in[10];
    const float* l2g = (const float*)d_in[11];
    const float* l2b = (const float*)d_in[12];
    const float* w1 = (const float*)d_in[13];
    const float* b1 = (const float*)d_in[14];
    const float* w2 = (const float*)d_in[15];
    const float* b2 = (const float*)d_in[16];
    float* out = (float*)d_out;

    void *p_melhi, *p_x1hi, *p_craw, *p_w1h, *p_w2h;
    cudaGetSymbolAddress(&p_melhi, g_melhi);
    cudaGetSymbolAddress(&p_x1hi, g_x1hi);
    cudaGetSymbolAddress(&p_craw, g_craw);
    cudaGetSymbolAddress(&p_w1h, g_w1h);
    cudaGetSymbolAddress(&p_w2h, g_w2h);

    cudaFuncSetAttribute(conv1_fused, cudaFuncAttributeMaxDynamicSharedMemorySize, CONV1_SMEM);
    cudaFuncSetAttribute(conv2_mma, cudaFuncAttributeMaxDynamicSharedMemorySize, CONV2_SMEM);

    mel_split_kernel<<<(int)(((size_t)BB * TT * 96 + 255) / 256), 256>>>(mels);
    wsplit_kernel<NMEL, 96><<<(KK * FILT * 96 + 255) / 256, 256>>>(c1w, (__half*)p_w1h);
    wsplit_kernel<FILT, FILT><<<(KK * FILT * FILT + 255) / 256, 256>>>(c2w, (__half*)p_w2h);
    scan_kernel<<<BB, 32>>>(durations, wpl);

    conv1_fused<<<dim3(TT / 64, BB), 256, CONV1_SMEM>>>(
        (const __half*)p_melhi, (const __half*)p_w1h,
        c1b, l1g, l1b, (__half*)p_x1hi);
    conv2_mma<<<dim3(TT / 128, 2, BB), 256, CONV2_SMEM>>>(
        (const __half*)p_x1hi, (const __half*)p_w2h, (float*)p_craw);

    lnpool_kernel<<<dim3(PP, BB), FILT>>>(durations, (const float*)p_craw,
        c2b, l2g, l2b);
    word_pool_kernel<<<dim3(WW, BB), FILT>>>(wpl);
    mlp_kernel<<<dim3(WW / 32, BB), 256>>>(w1, b1, w2, b2);
    expand_kernel<<<dim3(PP, BB), PDIM>>>(mask, out);
}

// round 14
// speedup vs baseline: 1.6023x; 1.0949x over previous
#include <cuda_runtime.h>
#include <cuda_fp16.h>
#include <cstdint>

#define BB 32
#define TT 4096
#define PP 512
#define WW 128
#define NMEL 80
#define FILT 256
#define PDIM 64
#define KK 9
#define PAD 4

// ---- conv2 (M=128 x N=128) ----
#define STR 40
#define A_ROWS 136
#define A_CP 5440
#define B_CP 5120
#define OFF_B (2 * A_CP)              // 10880 elems
#define CONV2_SMEM ((OFF_B + 6 * B_CP) * 2)   // 83200 B -> 2 CTAs/SM

// ---- conv1 fused (M=64 x N=256) ----
#define C1_AROWS 72
#define C1_ACP (C1_AROWS * STR)       // 2880 elems
#define C1_BCP (FILT * STR)           // 10240 elems
#define C1_OFFB (2 * C1_ACP)          // 5760 elems
#define CONV1_SMEM ((C1_OFFB + 3 * C1_BCP) * 2)  // 72960 B -> 2 CTAs/SM

// ---------------- device scratch ----------------------------------------------------
__device__ __half g_melhi[(size_t)BB * TT * 96];
__device__ __half g_x1hi[(size_t)BB * TT * FILT];
__device__ __half g_craw[(size_t)BB * TT * FILT];    // fp16: bias+relu applied
__device__ __half g_w1h[KK * FILT * 96];
__device__ __half g_w2h[KK * FILT * FILT];
__device__ float g_ph[(size_t)BB * PP * FILT];
__device__ float g_wd[(size_t)BB * WW * FILT];
__device__ float g_z [(size_t)BB * WW * PDIM];
__device__ int   g_pcum[BB * PP];
__device__ int   g_wcum[BB * WW];

// ---------------- helpers ------------------------------------------------------------
__device__ __forceinline__ uint32_t smem_u32(const void* p) {
    return (uint32_t)__cvta_generic_to_shared(p);
}
#define CP16(dst_u32, src_ptr) \
    asm volatile("cp.async.cg.shared.global [%0], [%1], 16;" :: "r"(dst_u32), "l"(src_ptr) : "memory")
#define CP_COMMIT() asm volatile("cp.async.commit_group;" ::: "memory")
#define CP_WAIT0()  asm volatile("cp.async.wait_group 0;" ::: "memory")
#define CP_WAIT1()  asm volatile("cp.async.wait_group 1;" ::: "memory")
#define CP_WAIT2()  asm volatile("cp.async.wait_group 2;" ::: "memory")
#define CP_WAIT4()  asm volatile("cp.async.wait_group 4;" ::: "memory")

#define MMA_F16(d, a, b) \
    asm volatile("mma.sync.aligned.m16n8k16.row.col.f32.f16.f16.f32 " \
        "{%0,%1,%2,%3},{%4,%5,%6,%7},{%8,%9},{%0,%1,%2,%3};" \
        : "+f"((d)[0]), "+f"((d)[1]), "+f"((d)[2]), "+f"((d)[3]) \
        : "r"((a)[0]), "r"((a)[1]), "r"((a)[2]), "r"((a)[3]), "r"((b)[0]), "r"((b)[1]))

#define LDM4(r0, r1, r2, r3, addr) \
    asm volatile("ldmatrix.sync.aligned.m8n8.x4.shared.b16 {%0,%1,%2,%3}, [%4];" \
        : "=r"(r0), "=r"(r1), "=r"(r2), "=r"(r3) : "r"(addr))

__device__ __forceinline__ uint32_t pack_hi2(float x0, float x1) {
    __half2 t(__float2half_rn(x0), __float2half_rn(x1));
    return *reinterpret_cast<uint32_t*>(&t);
}

// ---------------- prep kernels -------------------------------------------------------
__global__ void mel_split_kernel(const float* __restrict__ mels) {
    size_t i = (size_t)blockIdx.x * blockDim.x + threadIdx.x;
    if (i < (size_t)BB * TT * 96) {
        size_t t = i / 96;
        int ci = (int)(i % 96);
        float x = (ci < NMEL) ? mels[t * NMEL + ci] : 0.f;
        g_melhi[i] = __float2half_rn(x);
    }
}
__global__ void wsplit_both_kernel(const float* __restrict__ w1,
                                   const float* __restrict__ w2) {
    const int N1 = KK * FILT * 96;
    const int N2 = KK * FILT * FILT;
    int i = blockIdx.x * blockDim.x + threadIdx.x;
    if (i < N1) {
        int ci = i % 96, co = (i / 96) % FILT, tap = i / (96 * FILT);
        float x = (ci < NMEL) ? w1[(co * NMEL + ci) * KK + tap] : 0.f;
        g_w1h[i] = __float2half_rn(x);
    } else if (i - N1 < N2) {
        int j = i - N1;
        int ci = j % FILT, co = (j / FILT) % FILT, tap = j / (FILT * FILT);
        g_w2h[j] = __float2half_rn(w2[(co * FILT + ci) * KK + tap]);
    }
}
__global__ void scan_kernel(const int* __restrict__ dur, const int* __restrict__ wpl) {
    int b = blockIdx.x, lane = threadIdx.x;
    int v[16], s = 0;
#pragma unroll
    for (int i = 0; i < 16; i++) { v[i] = dur[b * PP + lane * 16 + i]; s += v[i]; }
    int inc = s;
#pragma unroll
    for (int off = 1; off < 32; off <<= 1) {
        int t = __shfl_up_sync(0xffffffffu, inc, off);
        if (lane >= off) inc += t;
    }
    int base = inc - s, run = 0;
#pragma unroll
    for (int i = 0; i < 16; i++) { run += v[i]; g_pcum[b * PP + lane * 16 + i] = base + run; }
    int w[4]; s = 0;
#pragma unroll
    for (int i = 0; i < 4; i++) { w[i] = wpl[b * WW + lane * 4 + i]; s += w[i]; }
    inc = s;
#pragma unroll
    for (int off = 1; off < 32; off <<= 1) {
        int t = __shfl_up_sync(0xffffffffu, inc, off);
        if (lane >= off) inc += t;
    }
    base = inc - s; run = 0;
#pragma unroll
    for (int i = 0; i < 4; i++) { run += w[i]; g_wcum[b * WW + lane * 4 + i] = base + run; }
}

// ---------------- conv1 fused: fp16 mma + bias + relu + LN -> fp16 hi ----------------
__global__ void __launch_bounds__(256, 2) conv1_fused(
    const __half* __restrict__ Ahi, const __half* __restrict__ Bh16,
    const float* __restrict__ bias, const float* __restrict__ gamma,
    const float* __restrict__ beta, __half* __restrict__ outh)
{
    constexpr int CIN = NMEL, CINP = 96, NST = 3 * KK;
    extern __shared__ __half smhf[];
    __shared__ float sB[FILT], sG[FILT], sE[FILT];
    __shared__ float s_m[64], s_r[64];

    const int tid = threadIdx.x;
    const int wid = tid >> 5, lane = tid & 31;
    const int wm = wid & 1, wn = wid >> 1;
    const int t0 = blockIdx.x * 64;
    const size_t bT = (size_t)blockIdx.y * TT;
    const uint32_t smb = smem_u32(smhf);

    if (tid < FILT) { sB[tid] = bias[tid]; sG[tid] = gamma[tid]; sE[tid] = beta[tid]; }

    float acc[2][8][4];
#pragma unroll
    for (int mt = 0; mt < 2; mt++)
#pragma unroll
        for (int nt = 0; nt < 8; nt++)
#pragma unroll
            for (int q = 0; q < 4; q++) acc[mt][nt][q] = 0.f;

    const int a_l = ((lane >> 3) & 1) * 8 + (lane & 7);
    const int a_k = (lane >> 4) * 8;
    const int b_l = (lane >> 4) * 8 + (lane & 7);
    const int b_k = ((lane >> 3) & 1) * 8;
    uint32_t aoff[2], boff[4];
#pragma unroll
    for (int mt = 0; mt < 2; mt++)
        aoff[mt] = ((wm * 32 + mt * 16 + a_l) * STR + a_k) * 2;
#pragma unroll
    for (int np = 0; np < 4; np++)
        boff[np] = ((wn * 64 + np * 16 + b_l) * STR + b_k) * 2;

    auto issue_loads = [&](int s) {
        int chunk = s / KK, tap = s - chunk * KK;
        int kc = CIN - chunk * 32; if (kc > 32) kc = 32;
        __half* sBp = smhf + C1_OFFB + (s % 3) * C1_BCP;
#pragma unroll
        for (int j = 0; j < 4; j++) {
            int q = tid + j * 256;
            int row = q >> 2, c16 = q & 3;
            if (c16 * 8 < kc) {
                const __half* src = Bh16
                    + ((size_t)tap * FILT + row) * CINP + chunk * 32 + c16 * 8;
                CP16(smem_u32(sBp + row * STR + c16 * 8), src);
            }
        }
        if (tap == 0) {
            __half* sA = smhf + (chunk & 1) * C1_ACP;
#pragma unroll
            for (int j = 0; j < 2; j++) {
                int q = tid + j * 256;
                if (q < 4 * C1_AROWS) {
                    int row = q >> 2, c16 = q & 3;
                    if (c16 * 8 >= kc) continue;
                    int trow = t0 + row - PAD;
                    __half* dst = sA + row * STR + c16 * 8;
                    if (trow >= 0 && trow < TT) {
                        const __half* src = Ahi
                            + (bT + trow) * CINP + chunk * 32 + c16 * 8;
                        CP16(smem_u32(dst), src);
                    } else {
                        *(uint4*)dst = make_uint4(0, 0, 0, 0);
                    }
                }
            }
        }
    };

    issue_loads(0); CP_COMMIT();
    issue_loads(1); CP_COMMIT();

    for (int s = 0; s < NST; s++) {
        if (s + 1 < NST) CP_WAIT1(); else CP_WAIT0();
        __syncthreads();
        if (s + 2 < NST) { issue_loads(s + 2); CP_COMMIT(); }

        int chunk = s / KK, tap = s - chunk * KK;
        uint32_t aAh = smb + (chunk & 1) * (C1_ACP * 2) + tap * (STR * 2);
        uint32_t aB  = smb + (C1_OFFB + (s % 3) * C1_BCP) * 2;

        auto do_kk = [&](int kk) {
            uint32_t ah[2][4], bh[8][2];
#pragma unroll
            for (int mt = 0; mt < 2; mt++)
                LDM4(ah[mt][0], ah[mt][1], ah[mt][2], ah[mt][3], aAh + aoff[mt] + kk * 32);
#pragma unroll
            for (int np = 0; np < 4; np++)
                LDM4(bh[2 * np][0], bh[2 * np][1], bh[2 * np + 1][0], bh[2 * np + 1][1],
                     aB + boff[np] + kk * 32);
#pragma unroll
            for (int mt = 0; mt < 2; mt++)
#pragma unroll
                for (int nt = 0; nt < 8; nt++) MMA_F16(acc[mt][nt], ah[mt], bh[nt]);
        };
        do_kk(0);
        if ((CIN - chunk * 32) >= 32) do_kk(1);
    }
    __syncthreads();

    float* st = (float*)smhf;
    const int r = lane >> 2, cq = lane & 3;
#pragma unroll
    for (int mt = 0; mt < 2; mt++) {
        int R0 = wm * 32 + mt * 16 + r;
#pragma unroll
        for (int nt = 0; nt < 8; nt++) {
            int C = wn * 64 + nt * 8 + 2 * cq;
            st[R0 * FILT + C]           = fmaxf(acc[mt][nt][0] + sB[C], 0.f);
            st[R0 * FILT + C + 1]       = fmaxf(acc[mt][nt][1] + sB[C + 1], 0.f);
            st[(R0 + 8) * FILT + C]     = fmaxf(acc[mt][nt][2] + sB[C], 0.f);
            st[(R0 + 8) * FILT + C + 1] = fmaxf(acc[mt][nt][3] + sB[C + 1], 0.f);
        }
    }
    __syncthreads();

#pragma unroll
    for (int rr = 0; rr < 8; rr++) {
        int row = wid * 8 + rr;
        float4 u = ((const float4*)st)[row * 64 + lane];
        float4 v = ((const float4*)st)[row * 64 + lane + 32];
        float s = u.x + u.y + u.z + u.w + v.x + v.y + v.z + v.w;
        float q = u.x * u.x + u.y * u.y + u.z * u.z + u.w * u.w
                + v.x * v.x + v.y * v.y + v.z * v.z + v.w * v.w;
#pragma unroll
        for (int off = 16; off > 0; off >>= 1) {
            s += __shfl_xor_sync(0xffffffffu, s, off);
            q += __shfl_xor_sync(0xffffffffu, q, off);
        }
        if (lane == 0) {
            float m = s * (1.f / FILT);
            s_m[row] = m;
            s_r[row] = rsqrtf(q * (1.f / FILT) - m * m + 1e-5f);
        }
    }
    __syncthreads();

#pragma unroll
    for (int j = 0; j < 16; j++) {
        int f4 = tid + j * 256;
        int row = f4 >> 6, c4 = f4 & 63;
        float4 v = ((const float4*)st)[f4];
        float m = s_m[row], rs = s_r[row];
        int C = c4 * 4;
        float y0 = (v.x - m) * rs * sG[C]     + sE[C];
        float y1 = (v.y - m) * rs * sG[C + 1] + sE[C + 1];
        float y2 = (v.z - m) * rs * sG[C + 2] + sE[C + 2];
        float y3 = (v.w - m) * rs * sG[C + 3] + sE[C + 3];
        size_t o = (bT + t0 + row) * FILT + C;
        *(uint2*)(outh + o) = make_uint2(pack_hi2(y0, y1), pack_hi2(y2, y3));
    }
}

// ---------------- conv2: fp16 mma, M=128 x N=128; epilogue bias+relu -> fp16 ---------
__global__ void __launch_bounds__(256, 2) conv2_mma(
    const __half* __restrict__ Ahi, const __half* __restrict__ Bh16,
    const float* __restrict__ bias, __half* __restrict__ outh)
{
    constexpr int CINP = FILT, NST = 8 * KK;   // 72
    extern __shared__ __half smhf[];

    const int tid = threadIdx.x;
    const int wid = tid >> 5, lane = tid & 31;
    const int wm = wid & 1, wn = wid >> 1;
    const int t0 = blockIdx.x * 128;
    const int n0 = blockIdx.y * 128;
    const size_t bT = (size_t)blockIdx.z * TT;
    const uint32_t smb = smem_u32(smhf);

    float acc[4][4][4];
#pragma unroll
    for (int mt = 0; mt < 4; mt++)
#pragma unroll
        for (int nt = 0; nt < 4; nt++)
#pragma unroll
            for (int q = 0; q < 4; q++) acc[mt][nt][q] = 0.f;

    const int a_l = ((lane >> 3) & 1) * 8 + (lane & 7);
    const int a_k = (lane >> 4) * 8;
    const int b_l = (lane >> 4) * 8 + (lane & 7);
    const int b_k = ((lane >> 3) & 1) * 8;
    uint32_t aoff[4], boff[2];
#pragma unroll
    for (int mt = 0; mt < 4; mt++)
        aoff[mt] = ((wm * 64 + mt * 16 + a_l) * STR + a_k) * 2;
#pragma unroll
    for (int np = 0; np < 2; np++)
        boff[np] = ((wn * 32 + np * 16 + b_l) * STR + b_k) * 2;

    auto issue_loads = [&](int s) {
        int chunk = s / KK, tap = s - chunk * KK;
        __half* sB = smhf + OFF_B + (s % 6) * B_CP;
#pragma unroll
        for (int j = 0; j < 2; j++) {
            int q = tid + j * 256;
            int row = q >> 2, c16 = q & 3;
            const __half* src = Bh16
                + ((size_t)tap * FILT + n0 + row) * CINP + chunk * 32 + c16 * 8;
            CP16(smem_u32(sB + row * STR + c16 * 8), src);
        }
        if (tap == 0) {
            __half* sA = smhf + (chunk & 1) * A_CP;
#pragma unroll
            for (int j = 0; j < 3; j++) {
                int q = tid + j * 256;
                if (q < 4 * A_ROWS) {
                    int row = q >> 2, c16 = q & 3;
                    int trow = t0 + row - PAD;
                    __half* dst = sA + row * STR + c16 * 8;
                    if (trow >= 0 && trow < TT) {
                        const __half* src = Ahi
                            + (bT + trow) * CINP + chunk * 32 + c16 * 8;
                        CP16(smem_u32(dst), src);
                    } else {
                        *(uint4*)dst = make_uint4(0, 0, 0, 0);
                    }
                }
            }
        }
    };

#pragma unroll
    for (int i = 0; i < 6; i++) { issue_loads(i); CP_COMMIT(); }

    auto compute_stage = [&](int s) {
        int chunk = s / KK, tap = s - chunk * KK;
        uint32_t aAh = smb + (chunk & 1) * (A_CP * 2) + tap * (STR * 2);
        uint32_t aBh = smb + (OFF_B + (s % 6) * B_CP) * 2;
#pragma unroll
        for (int kk = 0; kk < 2; kk++) {
            uint32_t ah[4][4], bh[4][2];
#pragma unroll
            for (int mt = 0; mt < 4; mt++)
                LDM4(ah[mt][0], ah[mt][1], ah[mt][2], ah[mt][3], aAh + aoff[mt] + kk * 32);
#pragma unroll
            for (int np = 0; np < 2; np++)
                LDM4(bh[2 * np][0], bh[2 * np][1], bh[2 * np + 1][0], bh[2 * np + 1][1],
                     aBh + boff[np] + kk * 32);
#pragma unroll
            for (int mt = 0; mt < 4; mt++)
#pragma unroll
                for (int nt = 0; nt < 4; nt++) MMA_F16(acc[mt][nt], ah[mt], bh[nt]);
        }
    };

    for (int p = 0; p < NST / 2; p++) {
        int s0 = 2 * p;
        int rem = NST - s0 - 2;
        if (rem >= 4) CP_WAIT4();
        else if (rem >= 2) CP_WAIT2();
        else CP_WAIT0();
        __syncthreads();
        if (s0 + 4 < NST) { issue_loads(s0 + 4); CP_COMMIT(); }
        if (s0 + 5 < NST) { issue_loads(s0 + 5); CP_COMMIT(); }
        compute_stage(s0);
        compute_stage(s0 + 1);
    }
    __syncthreads();

    // epilogue: stage acc to smem; then bias+relu -> fp16 global
    float* st = (float*)smhf;
    const int r = lane >> 2, cq = lane & 3;
#pragma unroll
    for (int mt = 0; mt < 4; mt++) {
        int R0 = wm * 64 + mt * 16 + r;
#pragma unroll
        for (int nt = 0; nt < 4; nt++) {
            int C = wn * 32 + nt * 8 + 2 * cq;
            st[R0 * 128 + C]           = acc[mt][nt][0];
            st[R0 * 128 + C + 1]       = acc[mt][nt][1];
            st[(R0 + 8) * 128 + C]     = acc[mt][nt][2];
            st[(R0 + 8) * 128 + C + 1] = acc[mt][nt][3];
        }
    }
    __syncthreads();
    {
        int c4 = tid & 31;                     // fixed columns for this thread
        float b0 = bias[n0 + c4 * 4];
        float b1 = bias[n0 + c4 * 4 + 1];
        float b2 = bias[n0 + c4 * 4 + 2];
        float b3 = bias[n0 + c4 * 4 + 3];
#pragma unroll
        for (int i = 0; i < 16; i++) {
            int f4 = tid + i * 256;
            int row = f4 >> 5;
            float4 v = ((const float4*)st)[f4];
            float y0 = fmaxf(v.x + b0, 0.f), y1 = fmaxf(v.y + b1, 0.f);
            float y2 = fmaxf(v.z + b2, 0.f), y3 = fmaxf(v.w + b3, 0.f);
            *(uint2*)(outh + (bT + t0 + row) * FILT + n0 + c4 * 4) =
                make_uint2(pack_hi2(y0, y1), pack_hi2(y2, y3));
        }
    }
}

// ---------------- fused LN + phone mean pool (warp-per-frame) ------------------------
// Input craw fp16 already has bias+relu applied. Block = one phone, 8 warps.
__global__ void __launch_bounds__(256) lnpool_kernel(
    const int* __restrict__ dur, const __half* __restrict__ gc,
    const float* __restrict__ gamma, const float* __restrict__ beta)
{
    __shared__ float sG[FILT], sE[FILT];
    __shared__ float red[8 * FILT];           // per-warp partial accum
    int b = blockIdx.y, p = blockIdx.x, tid = threadIdx.x;
    int w = tid >> 5, lane = tid & 31;
    sG[tid] = gamma[tid]; sE[tid] = beta[tid];
    __syncthreads();

    int start = p ? g_pcum[b * PP + p - 1] : 0;
    int end = g_pcum[b * PP + p];
    if (start > TT) start = TT;
    if (end > TT) end = TT;

    int c0 = lane * 8;
    float a[8];
#pragma unroll
    for (int j = 0; j < 8; j++) a[j] = 0.f;

    for (int t = start + w; t < end; t += 8) {
        uint4 u = *(const uint4*)(gc + ((size_t)(b * TT + t)) * FILT + c0);
        const __half2* hp = (const __half2*)&u;
        float x[8];
#pragma unroll
        for (int j = 0; j < 4; j++) {
            float2 f = __half22float2(hp[j]);
            x[2 * j] = f.x; x[2 * j + 1] = f.y;
        }
        float s = 0.f, q = 0.f;
#pragma unroll
        for (int j = 0; j < 8; j++) { s += x[j]; q += x[j] * x[j]; }
#pragma unroll
        for (int off = 16; off > 0; off >>= 1) {
            s += __shfl_xor_sync(0xffffffffu, s, off);
            q += __shfl_xor_sync(0xffffffffu, q, off);
        }
        float m = s * (1.f / FILT);
        float rs = rsqrtf(q * (1.f / FILT) - m * m + 1e-5f);
#pragma unroll
        for (int j = 0; j < 8; j++)
            a[j] += (x[j] - m) * rs * sG[c0 + j] + sE[c0 + j];
    }
#pragma unroll
    for (int j = 0; j < 8; j++) red[w * FILT + c0 + j] = a[j];
    __syncthreads();

    int c = tid;
    float sum = 0.f;
#pragma unroll
    for (int w8 = 0; w8 < 8; w8++) sum += red[w8 * FILT + c];
    int d = dur[b * PP + p]; if (d < 1) d = 1;
    g_ph[((size_t)(b * PP + p)) * FILT + c] = sum / (float)d;
}

// ---------------- word pool / mlp / expand ------------------------------------------
__global__ void word_pool_kernel(const int* __restrict__ wpl) {
    int b = blockIdx.y, w = blockIdx.x, c = threadIdx.x;
    int start = w ? g_wcum[b * WW + w - 1] : 0;
    int end = g_wcum[b * WW + w];
    if (start > PP) start = PP;
    if (end > PP) end = PP;
    float s = 0.f;
    for (int p = start; p < end; p++) s += g_ph[((size_t)(b * PP + p)) * FILT + c];
    int d = wpl[b * WW + w]; if (d < 1) d = 1;
    g_wd[((size_t)(b * WW + w)) * FILT + c] = s / (float)d;
}
__global__ void __launch_bounds__(256) mlp_kernel(
    const float* __restrict__ w1, const float* __restrict__ b1,
    const float* __restrict__ w2, const float* __restrict__ b2)
{
    __shared__ float sh[32 * FILT];
    int b = blockIdx.y, w0 = blockIdx.x * 32, o = threadIdx.x;
    for (int idx = o; idx < 32 * FILT; idx += 256)
        sh[idx] = g_wd[((size_t)(b * WW + w0)) * FILT + idx];
    __syncthreads();
    float acc[32];
    float bv = b1[o];
#pragma unroll
    for (int m = 0; m < 32; m++) acc[m] = bv;
    for (int i = 0; i < FILT; i++) {
        float wv = w1[i * FILT + o];
#pragma unroll
        for (int m = 0; m < 32; m++) acc[m] += sh[m * FILT + i] * wv;
    }
    __syncthreads();
#pragma unroll
    for (int m = 0; m < 32; m++) sh[m * FILT + o] = fmaxf(acc[m], 0.f);
    __syncthreads();
    int oo = o & (PDIM - 1);
    int mg = o >> 6;
    for (int m = mg * 8; m < mg * 8 + 8; m++) {
        float a = b2[oo];
        for (int i = 0; i < FILT; i++) a += sh[m * FILT + i] * w2[i * PDIM + oo];
        g_z[((size_t)(b * WW + w0 + m)) * PDIM + oo] = fmaxf(a, 0.f);
    }
}
__global__ void expand_kernel(const unsigned char* __restrict__ mask, float* __restrict__ out) {
    int b = blockIdx.y, p = blockIdx.x, o = threadIdx.x;
    const int* wc = g_wcum + b * WW;
    int lo = 0, hi = WW;
    while (lo < hi) { int mid = (lo + hi) >> 1; if (wc[mid] <= p) lo = mid + 1; else hi = mid; }
    int wid = lo; if (wid > WW - 1) wid = WW - 1;
    float v = g_z[((size_t)(b * WW + wid)) * PDIM + o];
    if (mask[b * PP + p]) v = 0.f;
    out[((size_t)(b * PP + p)) * PDIM + o] = v;
}

// ---------------- host launch -------------------------------------------------------
extern "C" void kernel_launch(void* const* d_in, const int* in_sizes, int n_in,
                              void* d_out, int out_size)
{
    const unsigned char* mask = (const unsigned char*)d_in[0];
    const float* mels = (const float*)d_in[1];
    const int* durations = (const int*)d_in[3];
    const int* wpl = (const int*)d_in[4];
    const float* c1w = (const float*)d_in[5];
    const float* c1b = (const float*)d_in[6];
    const float* l1g = (const float*)d_in[7];
    const float* l1b = (const float*)d_in[8];
    const float* c2w = (const float*)d_in[9];
    const float* c2b = (const float*)d_in[10];
    const float* l2g = (const float*)d_in[11];
    const float* l2b = (const float*)d_in[12];
    const float* w1 = (const float*)d_in[13];
    const float* b1 = (const float*)d_in[14];
    const float* w2 = (const float*)d_in[15];
    const float* b2 = (const float*)d_in[16];
    float* out = (float*)d_out;

    void *p_melhi, *p_x1hi, *p_craw, *p_w1h, *p_w2h;
    cudaGetSymbolAddress(&p_melhi, g_melhi);
    cudaGetSymbolAddress(&p_x1hi, g_x1hi);
    cudaGetSymbolAddress(&p_craw, g_craw);
    cudaGetSymbolAddress(&p_w1h, g_w1h);
    cudaGetSymbolAddress(&p_w2h, g_w2h);

    cudaFuncSetAttribute(conv1_fused, cudaFuncAttributeMaxDynamicSharedMemorySize, CONV1_SMEM);
    cudaFuncSetAttribute(conv2_mma, cudaFuncAttributeMaxDynamicSharedMemorySize, CONV2_SMEM);

    mel_split_kernel<<<(int)(((size_t)BB * TT * 96 + 255) / 256), 256>>>(mels);
    wsplit_both_kernel<<<(KK * FILT * (96 + FILT) + 255) / 256, 256>>>(c1w, c2w);
    scan_kernel<<<BB, 32>>>(durations, wpl);

    conv1_fused<<<dim3(TT / 64, BB), 256, CONV1_SMEM>>>(
        (const __half*)p_melhi, (const __half*)p_w1h,
        c1b, l1g, l1b, (__half*)p_x1hi);
    conv2_mma<<<dim3(TT / 128, 2, BB), 256, CONV2_SMEM>>>(
        (const __half*)p_x1hi, (const __half*)p_w2h, c2b, (__half*)p_craw);

    lnpool_kernel<<<dim3(PP, BB), FILT>>>(durations, (const __half*)p_craw, l2g, l2b);
    word_pool_kernel<<<dim3(WW, BB), FILT>>>(wpl);
    mlp_kernel<<<dim3(WW / 32, BB), 256>>>(w1, b1, w2, b2);
    expand_kernel<<<dim3(PP, BB), PDIM>>>(mask, out);
}

// round 15
// speedup vs baseline: 1.6325x; 1.0189x over previous
#include <cuda_runtime.h>
#include <cuda_fp16.h>
#include <cstdint>

#define BB 32
#define TT 4096
#define PP 512
#define WW 128
#define NMEL 80
#define FILT 256
#define PDIM 64
#define KK 9
#define PAD 4

// ---- conv2 (M=128 x N=128), K-chunk 64 ----
#define STR2 72
#define A_ROWS 136
#define A_CP2 (A_ROWS * STR2)          // 9792 elems
#define B_CP2 (128 * STR2)             // 9216 elems
#define OFF_B2 (2 * A_CP2)             // 19584
#define CONV2_SMEM ((OFF_B2 + 3 * B_CP2) * 2)   // 94464 B -> 2 CTAs/SM

// ---- conv1 fused (M=64 x N=256), K-chunk 48 ----
#define C1_STR 56
#define C1_AROWS 72
#define C1_ACP (C1_AROWS * C1_STR)     // 4032 elems
#define C1_BCP (FILT * C1_STR)         // 14336 elems
#define C1_OFFB (2 * C1_ACP)           // 8064
#define CONV1_SMEM ((C1_OFFB + 3 * C1_BCP) * 2)  // 102144 B -> 2 CTAs/SM

// ---------------- device scratch ----------------------------------------------------
__device__ __half g_melhi[(size_t)BB * TT * 96];
__device__ __half g_x1hi[(size_t)BB * TT * FILT];
__device__ __half g_craw[(size_t)BB * TT * FILT];    // fp16: bias+relu applied
__device__ __half g_w1h[KK * FILT * 96];
__device__ __half g_w2h[KK * FILT * FILT];
__device__ float g_ph[(size_t)BB * PP * FILT];
__device__ float g_wd[(size_t)BB * WW * FILT];
__device__ float g_z [(size_t)BB * WW * PDIM];
__device__ int   g_pcum[BB * PP];
__device__ int   g_wcum[BB * WW];

// ---------------- helpers ------------------------------------------------------------
__device__ __forceinline__ uint32_t smem_u32(const void* p) {
    return (uint32_t)__cvta_generic_to_shared(p);
}
#define CP16(dst_u32, src_ptr) \
    asm volatile("cp.async.cg.shared.global [%0], [%1], 16;" :: "r"(dst_u32), "l"(src_ptr) : "memory")
#define CP_COMMIT() asm volatile("cp.async.commit_group;" ::: "memory")
#define CP_WAIT0()  asm volatile("cp.async.wait_group 0;" ::: "memory")
#define CP_WAIT1()  asm volatile("cp.async.wait_group 1;" ::: "memory")

#define MMA_F16(d, a, b) \
    asm volatile("mma.sync.aligned.m16n8k16.row.col.f32.f16.f16.f32 " \
        "{%0,%1,%2,%3},{%4,%5,%6,%7},{%8,%9},{%0,%1,%2,%3};" \
        : "+f"((d)[0]), "+f"((d)[1]), "+f"((d)[2]), "+f"((d)[3]) \
        : "r"((a)[0]), "r"((a)[1]), "r"((a)[2]), "r"((a)[3]), "r"((b)[0]), "r"((b)[1]))

#define LDM4(r0, r1, r2, r3, addr) \
    asm volatile("ldmatrix.sync.aligned.m8n8.x4.shared.b16 {%0,%1,%2,%3}, [%4];" \
        : "=r"(r0), "=r"(r1), "=r"(r2), "=r"(r3) : "r"(addr))

__device__ __forceinline__ uint32_t pack_hi2(float x0, float x1) {
    __half2 t(__float2half_rn(x0), __float2half_rn(x1));
    return *reinterpret_cast<uint32_t*>(&t);
}

// ---------------- prep kernels -------------------------------------------------------
__global__ void mel_split_kernel(const float* __restrict__ mels) {
    size_t i = (size_t)blockIdx.x * blockDim.x + threadIdx.x;
    if (i < (size_t)BB * TT * 96) {
        size_t t = i / 96;
        int ci = (int)(i % 96);
        float x = (ci < NMEL) ? mels[t * NMEL + ci] : 0.f;
        g_melhi[i] = __float2half_rn(x);
    }
}
__global__ void wsplit_both_kernel(const float* __restrict__ w1,
                                   const float* __restrict__ w2) {
    const int N1 = KK * FILT * 96;
    const int N2 = KK * FILT * FILT;
    int i = blockIdx.x * blockDim.x + threadIdx.x;
    if (i < N1) {
        int ci = i % 96, co = (i / 96) % FILT, tap = i / (96 * FILT);
        float x = (ci < NMEL) ? w1[(co * NMEL + ci) * KK + tap] : 0.f;
        g_w1h[i] = __float2half_rn(x);
    } else if (i - N1 < N2) {
        int j = i - N1;
        int ci = j % FILT, co = (j / FILT) % FILT, tap = j / (FILT * FILT);
        g_w2h[j] = __float2half_rn(w2[(co * FILT + ci) * KK + tap]);
    }
}
__global__ void scan_kernel(const int* __restrict__ dur, const int* __restrict__ wpl) {
    int b = blockIdx.x, lane = threadIdx.x;
    int v[16], s = 0;
#pragma unroll
    for (int i = 0; i < 16; i++) { v[i] = dur[b * PP + lane * 16 + i]; s += v[i]; }
    int inc = s;
#pragma unroll
    for (int off = 1; off < 32; off <<= 1) {
        int t = __shfl_up_sync(0xffffffffu, inc, off);
        if (lane >= off) inc += t;
    }
    int base = inc - s, run = 0;
#pragma unroll
    for (int i = 0; i < 16; i++) { run += v[i]; g_pcum[b * PP + lane * 16 + i] = base + run; }
    int w[4]; s = 0;
#pragma unroll
    for (int i = 0; i < 4; i++) { w[i] = wpl[b * WW + lane * 4 + i]; s += w[i]; }
    inc = s;
#pragma unroll
    for (int off = 1; off < 32; off <<= 1) {
        int t = __shfl_up_sync(0xffffffffu, inc, off);
        if (lane >= off) inc += t;
    }
    base = inc - s; run = 0;
#pragma unroll
    for (int i = 0; i < 4; i++) { run += w[i]; g_wcum[b * WW + lane * 4 + i] = base + run; }
}

// ---------------- conv1 fused: fp16 mma + bias + relu + LN -> fp16 hi ----------------
// M=64 x N=256, 8 warps (2m x 4n), 2 CTAs/SM. cin 80 (pad 96), K-chunks {48, 32}.
__global__ void __launch_bounds__(256, 2) conv1_fused(
    const __half* __restrict__ Ahi, const __half* __restrict__ Bh16,
    const float* __restrict__ bias, const float* __restrict__ gamma,
    const float* __restrict__ beta, __half* __restrict__ outh)
{
    constexpr int CINP = 96, NST = 2 * KK;   // 18 stages
    extern __shared__ __half smhf[];
    __shared__ float sB[FILT], sG[FILT], sE[FILT];
    __shared__ float s_m[64], s_r[64];

    const int tid = threadIdx.x;
    const int wid = tid >> 5, lane = tid & 31;
    const int wm = wid & 1, wn = wid >> 1;
    const int t0 = blockIdx.x * 64;
    const size_t bT = (size_t)blockIdx.y * TT;
    const uint32_t smb = smem_u32(smhf);

    if (tid < FILT) { sB[tid] = bias[tid]; sG[tid] = gamma[tid]; sE[tid] = beta[tid]; }

    float acc[2][8][4];
#pragma unroll
    for (int mt = 0; mt < 2; mt++)
#pragma unroll
        for (int nt = 0; nt < 8; nt++)
#pragma unroll
            for (int q = 0; q < 4; q++) acc[mt][nt][q] = 0.f;

    const int a_l = ((lane >> 3) & 1) * 8 + (lane & 7);
    const int a_k = (lane >> 4) * 8;
    const int b_l = (lane >> 4) * 8 + (lane & 7);
    const int b_k = ((lane >> 3) & 1) * 8;
    uint32_t aoff[2], boff[4];
#pragma unroll
    for (int mt = 0; mt < 2; mt++)
        aoff[mt] = ((wm * 32 + mt * 16 + a_l) * C1_STR + a_k) * 2;
#pragma unroll
    for (int np = 0; np < 4; np++)
        boff[np] = ((wn * 64 + np * 16 + b_l) * C1_STR + b_k) * 2;

    auto issue_loads = [&](int s) {
        int chunk = s / KK, tap = s - chunk * KK;
        int ci0 = chunk * 48;
        int kc = chunk ? 32 : 48;                       // real channels this chunk
        __half* sBp = smhf + C1_OFFB + (s % 3) * C1_BCP;
#pragma unroll
        for (int j = 0; j < 6; j++) {
            int q = tid + j * 256;                      // 256 rows x 6 c16 = 1536
            int row = q / 6, c16 = q % 6;
            if (c16 * 8 < kc) {
                const __half* src = Bh16
                    + ((size_t)tap * FILT + row) * CINP + ci0 + c16 * 8;
                CP16(smem_u32(sBp + row * C1_STR + c16 * 8), src);
            }
        }
        if (tap == 0) {
            __half* sA = smhf + (chunk & 1) * C1_ACP;
#pragma unroll
            for (int j = 0; j < 2; j++) {
                int q = tid + j * 256;
                if (q < 6 * C1_AROWS) {                 // 432
                    int row = q / 6, c16 = q % 6;
                    if (c16 * 8 >= kc) continue;
                    int trow = t0 + row - PAD;
                    __half* dst = sA + row * C1_STR + c16 * 8;
                    if (trow >= 0 && trow < TT) {
                        const __half* src = Ahi
                            + (bT + trow) * CINP + ci0 + c16 * 8;
                        CP16(smem_u32(dst), src);
                    } else {
                        *(uint4*)dst = make_uint4(0, 0, 0, 0);
                    }
                }
            }
        }
    };

    issue_loads(0); CP_COMMIT();
    issue_loads(1); CP_COMMIT();

    for (int s = 0; s < NST; s++) {
        if (s + 1 < NST) CP_WAIT1(); else CP_WAIT0();
        __syncthreads();
        if (s + 2 < NST) { issue_loads(s + 2); CP_COMMIT(); }

        int chunk = s / KK, tap = s - chunk * KK;
        uint32_t aAh = smb + (chunk & 1) * (C1_ACP * 2) + tap * (C1_STR * 2);
        uint32_t aB  = smb + (C1_OFFB + (s % 3) * C1_BCP) * 2;
        int kkmax = chunk ? 2 : 3;

        for (int kk = 0; kk < kkmax; kk++) {
            uint32_t ah[2][4], bh[8][2];
#pragma unroll
            for (int mt = 0; mt < 2; mt++)
                LDM4(ah[mt][0], ah[mt][1], ah[mt][2], ah[mt][3], aAh + aoff[mt] + kk * 32);
#pragma unroll
            for (int np = 0; np < 4; np++)
                LDM4(bh[2 * np][0], bh[2 * np][1], bh[2 * np + 1][0], bh[2 * np + 1][1],
                     aB + boff[np] + kk * 32);
#pragma unroll
            for (int mt = 0; mt < 2; mt++)
#pragma unroll
                for (int nt = 0; nt < 8; nt++) MMA_F16(acc[mt][nt], ah[mt], bh[nt]);
        }
    }
    __syncthreads();

    float* st = (float*)smhf;                 // 64 x 256 fp32 = 64 KB
    const int r = lane >> 2, cq = lane & 3;
#pragma unroll
    for (int mt = 0; mt < 2; mt++) {
        int R0 = wm * 32 + mt * 16 + r;
#pragma unroll
        for (int nt = 0; nt < 8; nt++) {
            int C = wn * 64 + nt * 8 + 2 * cq;
            st[R0 * FILT + C]           = fmaxf(acc[mt][nt][0] + sB[C], 0.f);
            st[R0 * FILT + C + 1]       = fmaxf(acc[mt][nt][1] + sB[C + 1], 0.f);
            st[(R0 + 8) * FILT + C]     = fmaxf(acc[mt][nt][2] + sB[C], 0.f);
            st[(R0 + 8) * FILT + C + 1] = fmaxf(acc[mt][nt][3] + sB[C + 1], 0.f);
        }
    }
    __syncthreads();

#pragma unroll
    for (int rr = 0; rr < 8; rr++) {
        int row = wid * 8 + rr;
        float4 u = ((const float4*)st)[row * 64 + lane];
        float4 v = ((const float4*)st)[row * 64 + lane + 32];
        float s = u.x + u.y + u.z + u.w + v.x + v.y + v.z + v.w;
        float q = u.x * u.x + u.y * u.y + u.z * u.z + u.w * u.w
                + v.x * v.x + v.y * v.y + v.z * v.z + v.w * v.w;
#pragma unroll
        for (int off = 16; off > 0; off >>= 1) {
            s += __shfl_xor_sync(0xffffffffu, s, off);
            q += __shfl_xor_sync(0xffffffffu, q, off);
        }
        if (lane == 0) {
            float m = s * (1.f / FILT);
            s_m[row] = m;
            s_r[row] = rsqrtf(q * (1.f / FILT) - m * m + 1e-5f);
        }
    }
    __syncthreads();

#pragma unroll
    for (int j = 0; j < 16; j++) {
        int f4 = tid + j * 256;               // 4096 float4 = 64x256
        int row = f4 >> 6, c4 = f4 & 63;
        float4 v = ((const float4*)st)[f4];
        float m = s_m[row], rs = s_r[row];
        int C = c4 * 4;
        float y0 = (v.x - m) * rs * sG[C]     + sE[C];
        float y1 = (v.y - m) * rs * sG[C + 1] + sE[C + 1];
        float y2 = (v.z - m) * rs * sG[C + 2] + sE[C + 2];
        float y3 = (v.w - m) * rs * sG[C + 3] + sE[C + 3];
        size_t o = (bT + t0 + row) * FILT + C;
        *(uint2*)(outh + o) = make_uint2(pack_hi2(y0, y1), pack_hi2(y2, y3));
    }
}

// ---------------- conv2: fp16 mma, M=128 x N=128, K-chunk 64; bias+relu -> fp16 ------
__global__ void __launch_bounds__(256, 2) conv2_mma(
    const __half* __restrict__ Ahi, const __half* __restrict__ Bh16,
    const float* __restrict__ bias, __half* __restrict__ outh)
{
    constexpr int CINP = FILT, NST = 4 * KK;   // 36 stages
    extern __shared__ __half smhf[];

    const int tid = threadIdx.x;
    const int wid = tid >> 5, lane = tid & 31;
    const int wm = wid & 1, wn = wid >> 1;
    const int t0 = blockIdx.x * 128;
    const int n0 = blockIdx.y * 128;
    const size_t bT = (size_t)blockIdx.z * TT;
    const uint32_t smb = smem_u32(smhf);

    float acc[4][4][4];
#pragma unroll
    for (int mt = 0; mt < 4; mt++)
#pragma unroll
        for (int nt = 0; nt < 4; nt++)
#pragma unroll
            for (int q = 0; q < 4; q++) acc[mt][nt][q] = 0.f;

    const int a_l = ((lane >> 3) & 1) * 8 + (lane & 7);
    const int a_k = (lane >> 4) * 8;
    const int b_l = (lane >> 4) * 8 + (lane & 7);
    const int b_k = ((lane >> 3) & 1) * 8;
    uint32_t aoff[4], boff[2];
#pragma unroll
    for (int mt = 0; mt < 4; mt++)
        aoff[mt] = ((wm * 64 + mt * 16 + a_l) * STR2 + a_k) * 2;
#pragma unroll
    for (int np = 0; np < 2; np++)
        boff[np] = ((wn * 32 + np * 16 + b_l) * STR2 + b_k) * 2;

    auto issue_loads = [&](int s) {
        int chunk = s / KK, tap = s - chunk * KK;
        __half* sB = smhf + OFF_B2 + (s % 3) * B_CP2;
#pragma unroll
        for (int j = 0; j < 4; j++) {
            int q = tid + j * 256;                      // 128 rows x 8 c16 = 1024
            int row = q >> 3, c16 = q & 7;
            const __half* src = Bh16
                + ((size_t)tap * FILT + n0 + row) * CINP + chunk * 64 + c16 * 8;
            CP16(smem_u32(sB + row * STR2 + c16 * 8), src);
        }
        if (tap == 0) {
            __half* sA = smhf + (chunk & 1) * A_CP2;
#pragma unroll
            for (int j = 0; j < 5; j++) {
                int q = tid + j * 256;
                if (q < 8 * A_ROWS) {                   // 1088
                    int row = q >> 3, c16 = q & 7;
                    int trow = t0 + row - PAD;
                    __half* dst = sA + row * STR2 + c16 * 8;
                    if (trow >= 0 && trow < TT) {
                        const __half* src = Ahi
                            + (bT + trow) * CINP + chunk * 64 + c16 * 8;
                        CP16(smem_u32(dst), src);
                    } else {
                        *(uint4*)dst = make_uint4(0, 0, 0, 0);
                    }
                }
            }
        }
    };

    issue_loads(0); CP_COMMIT();
    issue_loads(1); CP_COMMIT();

    for (int s = 0; s < NST; s++) {
        if (s + 1 < NST) CP_WAIT1(); else CP_WAIT0();
        __syncthreads();
        if (s + 2 < NST) { issue_loads(s + 2); CP_COMMIT(); }

        int chunk = s / KK, tap = s - chunk * KK;
        uint32_t aAh = smb + (chunk & 1) * (A_CP2 * 2) + tap * (STR2 * 2);
        uint32_t aBh = smb + (OFF_B2 + (s % 3) * B_CP2) * 2;

#pragma unroll
        for (int kk = 0; kk < 4; kk++) {
            uint32_t ah[4][4], bh[4][2];
#pragma unroll
            for (int mt = 0; mt < 4; mt++)
                LDM4(ah[mt][0], ah[mt][1], ah[mt][2], ah[mt][3], aAh + aoff[mt] + kk * 32);
#pragma unroll
            for (int np = 0; np < 2; np++)
                LDM4(bh[2 * np][0], bh[2 * np][1], bh[2 * np + 1][0], bh[2 * np + 1][1],
                     aBh + boff[np] + kk * 32);
#pragma unroll
            for (int mt = 0; mt < 4; mt++)
#pragma unroll
                for (int nt = 0; nt < 4; nt++) MMA_F16(acc[mt][nt], ah[mt], bh[nt]);
        }
    }
    __syncthreads();

    // epilogue: stage acc to smem; then bias+relu -> fp16 global
    float* st = (float*)smhf;                 // 64 KB staging (fits 94464)
    const int r = lane >> 2, cq = lane & 3;
#pragma unroll
    for (int mt = 0; mt < 4; mt++) {
        int R0 = wm * 64 + mt * 16 + r;
#pragma unroll
        for (int nt = 0; nt < 4; nt++) {
            int C = wn * 32 + nt * 8 + 2 * cq;
            st[R0 * 128 + C]           = acc[mt][nt][0];
            st[R0 * 128 + C + 1]       = acc[mt][nt][1];
            st[(R0 + 8) * 128 + C]     = acc[mt][nt][2];
            st[(R0 + 8) * 128 + C + 1] = acc[mt][nt][3];
        }
    }
    __syncthreads();
    {
        int c4 = tid & 31;
        float b0 = bias[n0 + c4 * 4];
        float b1 = bias[n0 + c4 * 4 + 1];
        float b2 = bias[n0 + c4 * 4 + 2];
        float b3 = bias[n0 + c4 * 4 + 3];
#pragma unroll
        for (int i = 0; i < 16; i++) {
            int f4 = tid + i * 256;
            int row = f4 >> 5;
            float4 v = ((const float4*)st)[f4];
            float y0 = fmaxf(v.x + b0, 0.f), y1 = fmaxf(v.y + b1, 0.f);
            float y2 = fmaxf(v.z + b2, 0.f), y3 = fmaxf(v.w + b3, 0.f);
            *(uint2*)(outh + (bT + t0 + row) * FILT + n0 + c4 * 4) =
                make_uint2(pack_hi2(y0, y1), pack_hi2(y2, y3));
        }
    }
}

// ---------------- fused LN + phone mean pool (warp-per-frame) ------------------------
__global__ void __launch_bounds__(256) lnpool_kernel(
    const int* __restrict__ dur, const __half* __restrict__ gc,
    const float* __restrict__ gamma, const float* __restrict__ beta)
{
    __shared__ float sG[FILT], sE[FILT];
    __shared__ float red[8 * FILT];
    int b = blockIdx.y, p = blockIdx.x, tid = threadIdx.x;
    int w = tid >> 5, lane = tid & 31;
    sG[tid] = gamma[tid]; sE[tid] = beta[tid];
    __syncthreads();

    int start = p ? g_pcum[b * PP + p - 1] : 0;
    int end = g_pcum[b * PP + p];
    if (start > TT) start = TT;
    if (end > TT) end = TT;

    int c0 = lane * 8;
    float a[8];
#pragma unroll
    for (int j = 0; j < 8; j++) a[j] = 0.f;

    for (int t = start + w; t < end; t += 8) {
        uint4 u = *(const uint4*)(gc + ((size_t)(b * TT + t)) * FILT + c0);
        const __half2* hp = (const __half2*)&u;
        float x[8];
#pragma unroll
        for (int j = 0; j < 4; j++) {
            float2 f = __half22float2(hp[j]);
            x[2 * j] = f.x; x[2 * j + 1] = f.y;
        }
        float s = 0.f, q = 0.f;
#pragma unroll
        for (int j = 0; j < 8; j++) { s += x[j]; q += x[j] * x[j]; }
#pragma unroll
        for (int off = 16; off > 0; off >>= 1) {
            s += __shfl_xor_sync(0xffffffffu, s, off);
            q += __shfl_xor_sync(0xffffffffu, q, off);
        }
        float m = s * (1.f / FILT);
        float rs = rsqrtf(q * (1.f / FILT) - m * m + 1e-5f);
#pragma unroll
        for (int j = 0; j < 8; j++)
            a[j] += (x[j] - m) * rs * sG[c0 + j] + sE[c0 + j];
    }
#pragma unroll
    for (int j = 0; j < 8; j++) red[w * FILT + c0 + j] = a[j];
    __syncthreads();

    int c = tid;
    float sum = 0.f;
#pragma unroll
    for (int w8 = 0; w8 < 8; w8++) sum += red[w8 * FILT + c];
    int d = dur[b * PP + p]; if (d < 1) d = 1;
    g_ph[((size_t)(b * PP + p)) * FILT + c] = sum / (float)d;
}

// ---------------- word pool / mlp / expand ------------------------------------------
__global__ void word_pool_kernel(const int* __restrict__ wpl) {
    int b = blockIdx.y, w = blockIdx.x, c = threadIdx.x;
    int start = w ? g_wcum[b * WW + w - 1] : 0;
    int end = g_wcum[b * WW + w];
    if (start > PP) start = PP;
    if (end > PP) end = PP;
    float s = 0.f;
    for (int p = start; p < end; p++) s += g_ph[((size_t)(b * PP + p)) * FILT + c];
    int d = wpl[b * WW + w]; if (d < 1) d = 1;
    g_wd[((size_t)(b * WW + w)) * FILT + c] = s / (float)d;
}
__global__ void __launch_bounds__(256) mlp_kernel(
    const float* __restrict__ w1, const float* __restrict__ b1,
    const float* __restrict__ w2, const float* __restrict__ b2)
{
    __shared__ float sh[32 * FILT];
    int b = blockIdx.y, w0 = blockIdx.x * 32, o = threadIdx.x;
    for (int idx = o; idx < 32 * FILT; idx += 256)
        sh[idx] = g_wd[((size_t)(b * WW + w0)) * FILT + idx];
    __syncthreads();
    float acc[32];
    float bv = b1[o];
#pragma unroll
    for (int m = 0; m < 32; m++) acc[m] = bv;
    for (int i = 0; i < FILT; i++) {
        float wv = w1[i * FILT + o];
#pragma unroll
        for (int m = 0; m < 32; m++) acc[m] += sh[m * FILT + i] * wv;
    }
    __syncthreads();
#pragma unroll
    for (int m = 0; m < 32; m++) sh[m * FILT + o] = fmaxf(acc[m], 0.f);
    __syncthreads();
    int oo = o & (PDIM - 1);
    int mg = o >> 6;
    for (int m = mg * 8; m < mg * 8 + 8; m++) {
        float a = b2[oo];
        for (int i = 0; i < FILT; i++) a += sh[m * FILT + i] * w2[i * PDIM + oo];
        g_z[((size_t)(b * WW + w0 + m)) * PDIM + oo] = fmaxf(a, 0.f);
    }
}
__global__ void expand_kernel(const unsigned char* __restrict__ mask, float* __restrict__ out) {
    int b = blockIdx.y, p = blockIdx.x, o = threadIdx.x;
    const int* wc = g_wcum + b * WW;
    int lo = 0, hi = WW;
    while (lo < hi) { int mid = (lo + hi) >> 1; if (wc[mid] <= p) lo = mid + 1; else hi = mid; }
    int wid = lo; if (wid > WW - 1) wid = WW - 1;
    float v = g_z[((size_t)(b * WW + wid)) * PDIM + o];
    if (mask[b * PP + p]) v = 0.f;
    out[((size_t)(b * PP + p)) * PDIM + o] = v;
}

// ---------------- host launch -------------------------------------------------------
extern "C" void kernel_launch(void* const* d_in, const int* in_sizes, int n_in,
                              void* d_out, int out_size)
{
    const unsigned char* mask = (const unsigned char*)d_in[0];
    const float* mels = (const float*)d_in[1];
    const int* durations = (const int*)d_in[3];
    const int* wpl = (const int*)d_in[4];
    const float* c1w = (const float*)d_in[5];
    const float* c1b = (const float*)d_in[6];
    const float* l1g = (const float*)d_in[7];
    const float* l1b = (const float*)d_in[8];
    const float* c2w = (const float*)d_in[9];
    const float* c2b = (const float*)d_in[10];
    const float* l2g = (const float*)d_in[11];
    const float* l2b = (const float*)d_in[12];
    const float* w1 = (const float*)d_in[13];
    const float* b1 = (const float*)d_in[14];
    const float* w2 = (const float*)d_in[15];
    const float* b2 = (const float*)d_in[16];
    float* out = (float*)d_out;

    void *p_melhi, *p_x1hi, *p_craw, *p_w1h, *p_w2h;
    cudaGetSymbolAddress(&p_melhi, g_melhi);
    cudaGetSymbolAddress(&p_x1hi, g_x1hi);
    cudaGetSymbolAddress(&p_craw, g_craw);
    cudaGetSymbolAddress(&p_w1h, g_w1h);
    cudaGetSymbolAddress(&p_w2h, g_w2h);

    cudaFuncSetAttribute(conv1_fused, cudaFuncAttributeMaxDynamicSharedMemorySize, CONV1_SMEM);
    cudaFuncSetAttribute(conv2_mma, cudaFuncAttributeMaxDynamicSharedMemorySize, CONV2_SMEM);

    mel_split_kernel<<<(int)(((size_t)BB * TT * 96 + 255) / 256), 256>>>(mels);
    wsplit_both_kernel<<<(KK * FILT * (96 + FILT) + 255) / 256, 256>>>(c1w, c2w);
    scan_kernel<<<BB, 32>>>(durations, wpl);

    conv1_fused<<<dim3(TT / 64, BB), 256, CONV1_SMEM>>>(
        (const __half*)p_melhi, (const __half*)p_w1h,
        c1b, l1g, l1b, (__half*)p_x1hi);
    conv2_mma<<<dim3(TT / 128, 2, BB), 256, CONV2_SMEM>>>(
        (const __half*)p_x1hi, (const __half*)p_w2h, c2b, (__half*)p_craw);

    lnpool_kernel<<<dim3(PP, BB), FILT>>>(durations, (const __half*)p_craw, l2g, l2b);
    word_pool_kernel<<<dim3(WW, BB), FILT>>>(wpl);
    mlp_kernel<<<dim3(WW / 32, BB), 256>>>(w1, b1, w2, b2);
    expand_kernel<<<dim3(PP, BB), PDIM>>>(mask, out);
}